// round 13
// baseline (speedup 1.0000x reference)
#include <cuda_runtime.h>
#include <cuda_fp16.h>
#include <cstdint>

#define BB   128
#define TT   512
#define II   300
#define HH   150
#define G3   450
#define KK   6
#define CC   300
#define THD  20
#define CLS  5

#define KP   320
#define MM   (BB * TT)

#define JPAD  464
#define KPAD2 160
#define MTILES 29
#define SCTH  928    // 29 warps

// ---------------- scratch ----------------
__device__ float d_gi_f[(size_t)MM * G3];
__device__ float d_gi_b[(size_t)MM * G3];
__device__ float d_seq [(size_t)MM * 2 * HH];
__device__ float d_hidden[BB * 2 * HH];
__device__ __half d_Whh_h[2][JPAD * KPAD2];
__device__ __half d_Xh[(size_t)MM * KP];
__device__ __half d_Wh[2][512 * KP];
__device__ float d_bias2[KK * 2 * HH];
__device__ float d_context[BB * KK * 2 * HH];
__device__ float d_pooled [BB * KK * 2 * HH];
__device__ float d_regpart[BB];

__device__ __forceinline__ uint32_t smem_u32(const void* p) {
    uint32_t r;
    asm("{ .reg .u64 t; cvta.to.shared.u64 t, %1; cvt.u32.u64 %0, t; }" : "=r"(r) : "l"(p));
    return r;
}

__device__ __forceinline__ void mma16816(float* d, const uint32_t* a, uint32_t b0, uint32_t b1) {
    asm volatile(
        "mma.sync.aligned.m16n8k16.row.col.f32.f16.f16.f32 "
        "{%0,%1,%2,%3}, {%4,%5,%6,%7}, {%8,%9}, {%0,%1,%2,%3};"
        : "+f"(d[0]), "+f"(d[1]), "+f"(d[2]), "+f"(d[3])
        : "r"(a[0]), "r"(a[1]), "r"(a[2]), "r"(a[3]), "r"(b0), "r"(b1));
}

// ---------------- prep: Whh -> half [JPAD][KPAD2], zero padded ----------------
__global__ void prep_kernel(const float* __restrict__ Whh_f, const float* __restrict__ Whh_b) {
    int idx = blockIdx.x * blockDim.x + threadIdx.x;
    int tot = JPAD * KPAD2;
    if (idx < 2 * tot) {
        int d = idx / tot;
        int r = idx - d * tot;
        int j = r / KPAD2, i = r - j * KPAD2;
        const float* W = d ? Whh_b : Whh_f;
        d_Whh_h[d][r] = (j < G3 && i < HH) ? __float2half(W[j * HH + i]) : __float2half(0.f);
    }
}

// ---------------- convert X, Wih -> padded half ----------------
__global__ void convert_kernel(const float* __restrict__ X,
                               const float* __restrict__ Wf, const float* __restrict__ Wb) {
    int idx = blockIdx.x * blockDim.x + threadIdx.x;
    const int totX = MM * (KP / 2);
    if (idx < totX) {
        int m = idx / (KP / 2), kp = idx - m * (KP / 2);
        int k = kp * 2;
        float a = (k < II)     ? X[(size_t)m * II + k]     : 0.f;
        float b = (k + 1 < II) ? X[(size_t)m * II + k + 1] : 0.f;
        reinterpret_cast<__half2*>(d_Xh)[idx] = __floats2half2_rn(a, b);
    } else {
        int r = idx - totX;
        const int totW = 512 * (KP / 2);
        if (r < 2 * totW) {
            int d = r / totW;
            int rr = r - d * totW;
            int n = rr / (KP / 2), kp = rr - n * (KP / 2);
            int k = kp * 2;
            const float* W = d ? Wb : Wf;
            float a = (n < G3 && k < II)     ? W[(size_t)n * II + k]     : 0.f;
            float b = (n < G3 && k + 1 < II) ? W[(size_t)n * II + k + 1] : 0.f;
            reinterpret_cast<__half2*>(d_Wh[d])[rr] = __floats2half2_rn(a, b);
        }
    }
}

// ---------------- bias2 ----------------
__global__ void bias2_kernel(const float* __restrict__ ac, const float* __restrict__ Wattn,
                             const float* __restrict__ battn) {
    int k = blockIdx.x;
    __shared__ float as[CC];
    int tid = threadIdx.x;
    if (tid < CC) as[tid] = ac[k * CC + tid];
    __syncthreads();
    if (tid < 2 * HH) {
        float acc = battn[k * 2 * HH + tid];
        const float* w = Wattn + (size_t)k * (CC + 2 * HH) * (2 * HH) + tid;
        #pragma unroll 4
        for (int c = 0; c < CC; ++c) acc += as[c] * w[(size_t)c * (2 * HH)];
        d_bias2[k * 2 * HH + tid] = acc;
    }
}

// ---------------- gi GEMM: cp.async + ldmatrix + mma m16n8k16 (unchanged) -----------------
__global__ void __launch_bounds__(256, 2)
gemm_gi(const float* __restrict__ bf, const float* __restrict__ bb) {
    __shared__ __align__(16) __half Asm[2][128 * 40];
    __shared__ __align__(16) __half Bsm[2][64 * 40];
    int which = blockIdx.z;
    const __half* Wh  = d_Wh[which];
    const float* bias = which ? bb : bf;
    float* O          = which ? d_gi_b : d_gi_f;

    int m0 = blockIdx.y * 128;
    int n0 = blockIdx.x * 64;
    int tid = threadIdx.x;
    int wid = tid >> 5, lane = tid & 31;
    int warpM = (wid & 3) * 32;
    int warpN = (wid >> 2) * 32;
    int gr = lane >> 2, t4 = lane & 3;

    float acc[2][4][4];
    #pragma unroll
    for (int mt = 0; mt < 2; ++mt)
        #pragma unroll
        for (int nt = 0; nt < 4; ++nt)
            #pragma unroll
            for (int q = 0; q < 4; ++q) acc[mt][nt][q] = 0.f;

    int ar = tid >> 1, ac = (tid & 1) * 2;
    int br = tid >> 2, bc = tid & 3;
    const __half* Xsrc = d_Xh + (size_t)(m0 + ar) * KP + ac * 8;
    const __half* Wsrc = Wh   + (size_t)(n0 + br) * KP + bc * 8;
    uint32_t aBase = smem_u32(&Asm[0][0]);
    uint32_t bBase = smem_u32(&Bsm[0][0]);
    const uint32_t aBuf = 128 * 40 * 2, bBuf = 64 * 40 * 2;
    uint32_t aDst = aBase + (ar * 40 + ac * 8) * 2;
    uint32_t bDst = bBase + (br * 40 + bc * 8) * 2;

    const int NT = KP / 32;

    auto issue = [&](int it) {
        int buf = it & 1;
        const __half* as_ = Xsrc + it * 32;
        const __half* bs_ = Wsrc + it * 32;
        uint32_t ad = aDst + buf * aBuf;
        uint32_t bd = bDst + buf * bBuf;
        asm volatile(
            "cp.async.cg.shared.global [%0], [%1], 16;\n\t"
            "cp.async.cg.shared.global [%2], [%3], 16;\n\t"
            "cp.async.cg.shared.global [%4], [%5], 16;\n\t"
            "cp.async.commit_group;"
            :: "r"(ad), "l"(as_), "r"(ad + 16), "l"(as_ + 8), "r"(bd), "l"(bs_)
            : "memory");
    };

    uint32_t aRow[2], bRow[2];
    #pragma unroll
    for (int mt = 0; mt < 2; ++mt)
        aRow[mt] = ((warpM + mt * 16 + (lane & 15)) * 40 + ((lane >> 4) * 8)) * 2;
    #pragma unroll
    for (int p2 = 0; p2 < 2; ++p2)
        bRow[p2] = ((warpN + p2 * 16 + ((lane & 16) ? 8 : 0) + (lane & 7)) * 40
                    + ((lane & 8) ? 8 : 0)) * 2;

    issue(0);
    issue(1);

    for (int it = 0; it < NT; ++it) {
        if (it < NT - 1) asm volatile("cp.async.wait_group 1;" ::: "memory");
        else             asm volatile("cp.async.wait_group 0;" ::: "memory");
        __syncthreads();
        int buf = it & 1;
        uint32_t aB = aBase + buf * aBuf;
        uint32_t bB = bBase + buf * bBuf;
        #pragma unroll
        for (int kk = 0; kk < 32; kk += 16) {
            uint32_t a[2][4], b[2][4];
            #pragma unroll
            for (int mt = 0; mt < 2; ++mt)
                asm volatile("ldmatrix.sync.aligned.m8n8.x4.shared.b16 {%0,%1,%2,%3}, [%4];"
                             : "=r"(a[mt][0]), "=r"(a[mt][1]), "=r"(a[mt][2]), "=r"(a[mt][3])
                             : "r"(aB + aRow[mt] + kk * 2));
            #pragma unroll
            for (int p2 = 0; p2 < 2; ++p2)
                asm volatile("ldmatrix.sync.aligned.m8n8.x4.shared.b16 {%0,%1,%2,%3}, [%4];"
                             : "=r"(b[p2][0]), "=r"(b[p2][1]), "=r"(b[p2][2]), "=r"(b[p2][3])
                             : "r"(bB + bRow[p2] + kk * 2));
            #pragma unroll
            for (int mt = 0; mt < 2; ++mt)
                #pragma unroll
                for (int nt = 0; nt < 4; ++nt) {
                    uint32_t b0 = b[nt >> 1][(nt & 1) * 2];
                    uint32_t b1 = b[nt >> 1][(nt & 1) * 2 + 1];
                    asm volatile(
                        "mma.sync.aligned.m16n8k16.row.col.f32.f16.f16.f32 "
                        "{%0,%1,%2,%3}, {%4,%5,%6,%7}, {%8,%9}, {%0,%1,%2,%3};"
                        : "+f"(acc[mt][nt][0]), "+f"(acc[mt][nt][1]),
                          "+f"(acc[mt][nt][2]), "+f"(acc[mt][nt][3])
                        : "r"(a[mt][0]), "r"(a[mt][1]), "r"(a[mt][2]), "r"(a[mt][3]),
                          "r"(b0), "r"(b1));
                }
        }
        __syncthreads();
        if (it + 2 < NT) issue(it + 2);
    }

    #pragma unroll
    for (int mt = 0; mt < 2; ++mt) {
        #pragma unroll
        for (int hf = 0; hf < 2; ++hf) {
            int m = m0 + warpM + mt * 16 + gr + hf * 8;
            float* Orow = O + (size_t)m * G3;
            #pragma unroll
            for (int nt = 0; nt < 4; ++nt) {
                int col = n0 + warpN + nt * 8 + 2 * t4;
                if (col < G3) {
                    float v0 = acc[mt][nt][hf * 2 + 0] + bias[col];
                    float v1 = acc[mt][nt][hf * 2 + 1] + bias[col + 1];
                    *reinterpret_cast<float2*>(Orow + col) = make_float2(v0, v1);
                }
            }
        }
    }
}

// ---------------- persistent bidirectional GRU scan: 29 warps, one m-tile each -----------
__device__ __forceinline__ float sigm(float x) { return 1.f / (1.f + __expf(-x)); }
__device__ __forceinline__ float fast_tanh(float x) {
    float y; asm("tanh.approx.f32 %0, %1;" : "=f"(y) : "f"(x)); return y;
}

__global__ void __launch_bounds__(SCTH, 1)
scan_kernel(const float* __restrict__ bhh_f, const float* __restrict__ bhh_b) {
    __shared__ __align__(8) float2 ghb2[JPAD];
    __shared__ __align__(4) __half h_s[2][KPAD2];

    int bb  = blockIdx.x;
    int dir = bb >> 6;
    int p   = bb & 63;
    int b0  = 2 * p, b1 = b0 + 1;
    const float* gi  = dir ? d_gi_b : d_gi_f;
    const float* bhh = dir ? bhh_b : bhh_f;
    const __half* Wd = d_Whh_h[dir];
    int tid = threadIdx.x;               // 928
    int wid = tid >> 5, lane = tid & 31; // wid = tile index (0..28)
    int g = lane >> 2, tig = lane & 3;

    for (int i = tid; i < 2 * KPAD2; i += SCTH)
        reinterpret_cast<__half*>(h_s)[i] = __float2half(0.f);

    // A fragments for THIS warp's tile (constant across steps)
    uint32_t A[10][4];
    {
        const __half* r0 = Wd + (size_t)(wid * 16 + g) * KPAD2;
        const __half* r8 = r0 + 8 * KPAD2;
        #pragma unroll
        for (int kt = 0; kt < 10; ++kt) {
            int k0 = kt * 16 + tig * 2;
            A[kt][0] = *reinterpret_cast<const uint32_t*>(r0 + k0);
            A[kt][1] = *reinterpret_cast<const uint32_t*>(r8 + k0);
            A[kt][2] = *reinterpret_cast<const uint32_t*>(r0 + k0 + 8);
            A[kt][3] = *reinterpret_cast<const uint32_t*>(r8 + k0 + 8);
        }
    }

    // bias fragments
    float cba, cbb;
    {
        int m = wid * 16 + g;
        cba = (m < G3) ? bhh[m] : 0.f;
        cbb = (m + 8 < G3) ? bhh[m + 8] : 0.f;
    }

    const int e = tid;
    const bool ge = (e < 2 * HH);
    const int row = (e < HH) ? 0 : 1;
    const int jj  = e - row * HH;
    const size_t rowbase = (size_t)(row ? b1 : b0) * TT;
    const bool bld = (g < 2);    // lanes whose B column is a real batch row

    __syncthreads();

    // prologue: gi for step 0
    float g_r = 0.f, g_z = 0.f, g_n = 0.f;
    if (ge) {
        int t0 = dir ? (TT - 1) : 0;
        size_t gb = (rowbase + t0) * G3 + jj;
        g_r = gi[gb]; g_z = gi[gb + HH]; g_n = gi[gb + 2 * HH];
    }

    for (int s = 0; s < TT; ++s) {
        int t = dir ? (TT - 1 - s) : s;
        // prefetch gi for NEXT step
        float nr = 0.f, nz = 0.f, nn = 0.f;
        if (ge && s + 1 < TT) {
            int tn = dir ? (TT - 2 - s) : (s + 1);
            size_t gb = (rowbase + tn) * G3 + jj;
            nr = gi[gb]; nz = gi[gb + HH]; nn = gi[gb + 2 * HH];
        }

        // ---- MMA phase: 10 MMAs, 2 chains, B loaded just-in-time ----
        {
            float da[4] = {cba, cba, cbb, cbb};
            float db[4] = {0.f, 0.f, 0.f, 0.f};
            #pragma unroll
            for (int kt = 0; kt < 10; kt += 2) {
                uint32_t b00 = 0, b01 = 0, b10 = 0, b11 = 0;
                if (bld) {
                    const __half* hp0 = &h_s[g][kt * 16 + tig * 2];
                    b00 = *reinterpret_cast<const uint32_t*>(hp0);
                    b01 = *reinterpret_cast<const uint32_t*>(hp0 + 8);
                    const __half* hp1 = hp0 + 16;
                    b10 = *reinterpret_cast<const uint32_t*>(hp1);
                    b11 = *reinterpret_cast<const uint32_t*>(hp1 + 8);
                }
                mma16816(da, A[kt],     b00, b01);
                mma16816(db, A[kt + 1], b10, b11);
            }
            if (tig == 0) {
                int m = wid * 16 + g;
                ghb2[m]     = make_float2(da[0] + db[0], da[1] + db[1]);
                ghb2[m + 8] = make_float2(da[2] + db[2], da[3] + db[3]);
            }
        }
        __syncthreads();

        // ---- gate phase ----
        if (ge) {
            const float* gb = reinterpret_cast<const float*>(ghb2);
            float hr = gb[jj * 2 + row];
            float hz = gb[(jj + HH) * 2 + row];
            float hn = gb[(jj + 2 * HH) * 2 + row];
            float rg = sigm(g_r + hr);
            float zg = sigm(g_z + hz);
            float ng = fast_tanh(g_n + rg * hn);
            float hp = __half2float(h_s[row][jj]);
            float hv = (1.f - zg) * ng + zg * hp;
            h_s[row][jj] = __float2half(hv);
            d_seq[(rowbase + t) * (2 * HH) + dir * HH + jj] = hv;
        }
        __syncthreads();
        g_r = nr; g_z = nz; g_n = nn;
    }
    if (ge) {
        float hv = __half2float(h_s[row][jj]);
        d_hidden[(size_t)(row ? b1 : b0) * (2 * HH) + dir * HH + jj] = hv;
    }
}

// ---------------- context ----------------
__global__ void ctx_kernel(const float* __restrict__ Wattn) {
    int bk = blockIdx.x;
    int b = bk / KK, k = bk - b * KK;
    __shared__ float hs[2 * HH];
    int tid = threadIdx.x;
    if (tid < 2 * HH) hs[tid] = d_hidden[b * 2 * HH + tid];
    __syncthreads();
    if (tid < 2 * HH) {
        float acc = d_bias2[k * 2 * HH + tid];
        const float* w = Wattn + ((size_t)k * (CC + 2 * HH) + CC) * (2 * HH) + tid;
        #pragma unroll 4
        for (int c = 0; c < 2 * HH; ++c) acc += hs[c] * w[(size_t)c * (2 * HH)];
        d_context[((size_t)b * KK + k) * (2 * HH) + tid] = tanhf(acc);
    }
}

// ---------------- energy -> softmax(t) -> pooled ----------------
__global__ void pool_kernel() {
    int b = blockIdx.x;
    __shared__ float ctx[KK][2 * HH];
    __shared__ float en[TT][KK];
    int tid = threadIdx.x;              // 512
    int w = tid >> 5, lane = tid & 31;
    for (int i = tid; i < KK * 2 * HH; i += 512)
        ctx[i / (2 * HH)][i % (2 * HH)] = d_context[(size_t)b * KK * 2 * HH + i];
    __syncthreads();
    for (int t = w; t < TT; t += 16) {
        const float* srow = d_seq + ((size_t)b * TT + t) * (2 * HH);
        float pk[KK] = {0, 0, 0, 0, 0, 0};
        for (int d = lane; d < 2 * HH; d += 32) {
            float s = srow[d];
            #pragma unroll
            for (int k = 0; k < KK; ++k) pk[k] = fmaf(s, ctx[k][d], pk[k]);
        }
        #pragma unroll
        for (int k = 0; k < KK; ++k) {
            float v = pk[k];
            for (int off = 16; off; off >>= 1) v += __shfl_xor_sync(~0u, v, off);
            if (lane == 0) en[t][k] = v;
        }
    }
    __syncthreads();
    if (w < KK) {
        float mx = -1e30f;
        for (int t = lane; t < TT; t += 32) mx = fmaxf(mx, en[t][w]);
        for (int off = 16; off; off >>= 1) mx = fmaxf(mx, __shfl_xor_sync(~0u, mx, off));
        float sum = 0.f;
        for (int t = lane; t < TT; t += 32) { float e2 = __expf(en[t][w] - mx); en[t][w] = e2; sum += e2; }
        for (int off = 16; off; off >>= 1) sum += __shfl_xor_sync(~0u, sum, off);
        float inv = 1.f / sum;
        for (int t = lane; t < TT; t += 32) en[t][w] *= inv;
    }
    __syncthreads();
    for (int d = tid; d < 2 * HH; d += 512) {
        float acc[KK] = {0, 0, 0, 0, 0, 0};
        for (int t = 0; t < TT; ++t) {
            float s = d_seq[((size_t)b * TT + t) * (2 * HH) + d];
            #pragma unroll
            for (int k = 0; k < KK; ++k) acc[k] = fmaf(s, en[t][k], acc[k]);
        }
        #pragma unroll
        for (int k = 0; k < KK; ++k)
            d_pooled[((size_t)b * KK + k) * (2 * HH) + d] = acc[k];
    }
}

// ---------------- topic -> logits -> softmax ----------------
__global__ void topic_kernel(const float* __restrict__ Wtop, const float* __restrict__ btop,
                             const float* __restrict__ Wout, const float* __restrict__ bout,
                             float* __restrict__ out) {
    int b = blockIdx.x;
    __shared__ float ps[KK * 2 * HH];
    __shared__ float feats[KK * THD];
    __shared__ float lg[CLS];
    int tid = threadIdx.x;
    for (int i = tid; i < KK * 2 * HH; i += 128) ps[i] = d_pooled[(size_t)b * KK * 2 * HH + i];
    __syncthreads();
    if (tid < KK * THD) {
        int k = tid / THD, th = tid - k * THD;
        float acc = btop[tid];
        const float* wp = Wtop + (size_t)k * (2 * HH) * THD + th;
        #pragma unroll 4
        for (int d = 0; d < 2 * HH; ++d) acc += ps[k * 2 * HH + d] * wp[d * THD];
        feats[tid] = fmaxf(acc, 0.f);
    }
    __syncthreads();
    if (tid < CLS) {
        float acc = bout[tid];
        for (int e2 = 0; e2 < KK * THD; ++e2) acc += feats[e2] * Wout[e2 * CLS + tid];
        lg[tid] = acc;
    }
    __syncthreads();
    if (tid < CLS) {
        float mx = lg[0];
        #pragma unroll
        for (int c = 1; c < CLS; ++c) mx = fmaxf(mx, lg[c]);
        float sum = 0.f;
        #pragma unroll
        for (int c = 0; c < CLS; ++c) sum += __expf(lg[c] - mx);
        out[b * CLS + tid] = __expf(lg[tid] - mx) / sum;
    }
}

// ---------------- orthogonality regularizer ----------------
__global__ void reg_partial_kernel() {
    int b = blockIdx.x;
    __shared__ float cs[KK * 2 * HH];
    __shared__ float D[KK * KK];
    int tid = threadIdx.x;
    int w = tid >> 5, lane = tid & 31;
    for (int i = tid; i < KK * 2 * HH; i += 256) cs[i] = d_context[(size_t)b * KK * 2 * HH + i];
    __syncthreads();
    for (int p2 = w; p2 < KK * KK; p2 += 8) {
        int k = p2 / KK, j = p2 - k * KK;
        float v = 0.f;
        for (int d = lane; d < 2 * HH; d += 32) v += cs[k * 2 * HH + d] * cs[j * 2 * HH + d];
        for (int off = 16; off; off >>= 1) v += __shfl_xor_sync(~0u, v, off);
        if (lane == 0) D[p2] = v;
    }
    __syncthreads();
    if (tid == 0) {
        float nk[KK];
        #pragma unroll
        for (int k = 0; k < KK; ++k) nk[k] = fmaxf(sqrtf(D[k * KK + k]), 1e-12f);
        float S = 0.f;
        for (int k = 0; k < KK; ++k)
            for (int j = 0; j < KK; ++j) {
                float g = D[k * KK + j] / (nk[k] * nk[j]) - (k == j ? 1.f : 0.f);
                S += g * g;
            }
        d_regpart[b] = sqrtf(S);
    }
}

__global__ void reg_final_kernel(float* __restrict__ regout) {
    __shared__ float s[BB];
    int tid = threadIdx.x;
    s[tid] = d_regpart[tid];
    __syncthreads();
    for (int off = 64; off; off >>= 1) {
        if (tid < off) s[tid] += s[tid + off];
        __syncthreads();
    }
    if (tid == 0) *regout = s[0] / (float)BB;
}

// ---------------- launch ------------------------------------------------------------------
extern "C" void kernel_launch(void* const* d_in, const int* in_sizes, int n_in,
                              void* d_out, int out_size) {
    const float* x      = (const float*)d_in[0];
    const float* Wih_f  = (const float*)d_in[1];
    const float* Whh_f  = (const float*)d_in[2];
    const float* bih_f  = (const float*)d_in[3];
    const float* bhh_f  = (const float*)d_in[4];
    const float* Wih_b  = (const float*)d_in[5];
    const float* Whh_b  = (const float*)d_in[6];
    const float* bih_b  = (const float*)d_in[7];
    const float* bhh_b  = (const float*)d_in[8];
    const float* attn_c = (const float*)d_in[9];
    const float* Wattn  = (const float*)d_in[10];
    const float* battn  = (const float*)d_in[11];
    const float* Wtop   = (const float*)d_in[12];
    const float* btop   = (const float*)d_in[13];
    const float* Wout   = (const float*)d_in[14];
    const float* bout   = (const float*)d_in[15];
    float* out = (float*)d_out;

    prep_kernel<<<(2 * JPAD * KPAD2 + 255) / 256, 256>>>(Whh_f, Whh_b);
    const int npair = MM * (KP / 2) + 2 * 512 * (KP / 2);
    convert_kernel<<<(npair + 255) / 256, 256>>>(x, Wih_f, Wih_b);
    bias2_kernel<<<KK, 320>>>(attn_c, Wattn, battn);

    gemm_gi<<<dim3(8, 512, 2), 256>>>(bih_f, bih_b);

    scan_kernel<<<128, SCTH>>>(bhh_f, bhh_b);

    ctx_kernel<<<BB * KK, 320>>>(Wattn);
    pool_kernel<<<BB, 512>>>();
    topic_kernel<<<BB, 128>>>(Wtop, btop, Wout, bout, out);
    if (out_size > BB * CLS) {
        reg_partial_kernel<<<BB, 256>>>();
        reg_final_kernel<<<1, BB>>>(out + BB * CLS);
    }
}

// round 14
// speedup vs baseline: 1.2678x; 1.2678x over previous
#include <cuda_runtime.h>
#include <cuda_fp16.h>
#include <cstdint>

#define BB   128
#define TT   512
#define II   300
#define HH   150
#define G3   450
#define KK   6
#define CC   300
#define THD  20
#define CLS  5

#define KP   320
#define MM   (BB * TT)

#define JPAD  464
#define KPAD2 160
#define MTILES 29

// ---------------- scratch ----------------
__device__ float d_gi_f[(size_t)MM * G3];
__device__ float d_gi_b[(size_t)MM * G3];
__device__ float d_seq [(size_t)MM * 2 * HH];
__device__ float d_hidden[BB * 2 * HH];
__device__ __half d_Whh_h[2][JPAD * KPAD2];
__device__ __half d_Xh[(size_t)MM * KP];
__device__ __half d_Wh[2][512 * KP];
__device__ float d_bias2[KK * 2 * HH];
__device__ float d_context[BB * KK * 2 * HH];
__device__ float d_pooled [BB * KK * 2 * HH];
__device__ float d_regpart[BB];

__device__ __forceinline__ uint32_t smem_u32(const void* p) {
    uint32_t r;
    asm("{ .reg .u64 t; cvta.to.shared.u64 t, %1; cvt.u32.u64 %0, t; }" : "=r"(r) : "l"(p));
    return r;
}

__device__ __forceinline__ void mma16816(float* d, const uint32_t* a, uint32_t b0, uint32_t b1) {
    asm volatile(
        "mma.sync.aligned.m16n8k16.row.col.f32.f16.f16.f32 "
        "{%0,%1,%2,%3}, {%4,%5,%6,%7}, {%8,%9}, {%0,%1,%2,%3};"
        : "+f"(d[0]), "+f"(d[1]), "+f"(d[2]), "+f"(d[3])
        : "r"(a[0]), "r"(a[1]), "r"(a[2]), "r"(a[3]), "r"(b0), "r"(b1));
}

// ---------------- prep: Whh -> half [JPAD][KPAD2], zero padded ----------------
__global__ void prep_kernel(const float* __restrict__ Whh_f, const float* __restrict__ Whh_b) {
    int idx = blockIdx.x * blockDim.x + threadIdx.x;
    int tot = JPAD * KPAD2;
    if (idx < 2 * tot) {
        int d = idx / tot;
        int r = idx - d * tot;
        int j = r / KPAD2, i = r - j * KPAD2;
        const float* W = d ? Whh_b : Whh_f;
        d_Whh_h[d][r] = (j < G3 && i < HH) ? __float2half(W[j * HH + i]) : __float2half(0.f);
    }
}

// ---------------- convert X, Wih -> padded half ----------------
__global__ void convert_kernel(const float* __restrict__ X,
                               const float* __restrict__ Wf, const float* __restrict__ Wb) {
    int idx = blockIdx.x * blockDim.x + threadIdx.x;
    const int totX = MM * (KP / 2);
    if (idx < totX) {
        int m = idx / (KP / 2), kp = idx - m * (KP / 2);
        int k = kp * 2;
        float a = (k < II)     ? X[(size_t)m * II + k]     : 0.f;
        float b = (k + 1 < II) ? X[(size_t)m * II + k + 1] : 0.f;
        reinterpret_cast<__half2*>(d_Xh)[idx] = __floats2half2_rn(a, b);
    } else {
        int r = idx - totX;
        const int totW = 512 * (KP / 2);
        if (r < 2 * totW) {
            int d = r / totW;
            int rr = r - d * totW;
            int n = rr / (KP / 2), kp = rr - n * (KP / 2);
            int k = kp * 2;
            const float* W = d ? Wb : Wf;
            float a = (n < G3 && k < II)     ? W[(size_t)n * II + k]     : 0.f;
            float b = (n < G3 && k + 1 < II) ? W[(size_t)n * II + k + 1] : 0.f;
            reinterpret_cast<__half2*>(d_Wh[d])[rr] = __floats2half2_rn(a, b);
        }
    }
}

// ---------------- bias2 ----------------
__global__ void bias2_kernel(const float* __restrict__ ac, const float* __restrict__ Wattn,
                             const float* __restrict__ battn) {
    int k = blockIdx.x;
    __shared__ float as[CC];
    int tid = threadIdx.x;
    if (tid < CC) as[tid] = ac[k * CC + tid];
    __syncthreads();
    if (tid < 2 * HH) {
        float acc = battn[k * 2 * HH + tid];
        const float* w = Wattn + (size_t)k * (CC + 2 * HH) * (2 * HH) + tid;
        #pragma unroll 4
        for (int c = 0; c < CC; ++c) acc += as[c] * w[(size_t)c * (2 * HH)];
        d_bias2[k * 2 * HH + tid] = acc;
    }
}

// ---------------- gi GEMM: cp.async + ldmatrix + mma m16n8k16 (R10 version) ---------------
__global__ void __launch_bounds__(256, 2)
gemm_gi(const float* __restrict__ bf, const float* __restrict__ bb) {
    __shared__ __align__(16) __half Asm[2][128 * 40];
    __shared__ __align__(16) __half Bsm[2][64 * 40];
    int which = blockIdx.z;
    const __half* Wh  = d_Wh[which];
    const float* bias = which ? bb : bf;
    float* O          = which ? d_gi_b : d_gi_f;

    int m0 = blockIdx.y * 128;
    int n0 = blockIdx.x * 64;
    int tid = threadIdx.x;
    int wid = tid >> 5, lane = tid & 31;
    int warpM = (wid & 3) * 32;
    int warpN = (wid >> 2) * 32;
    int gr = lane >> 2, t4 = lane & 3;

    float acc[2][4][4];
    #pragma unroll
    for (int mt = 0; mt < 2; ++mt)
        #pragma unroll
        for (int nt = 0; nt < 4; ++nt)
            #pragma unroll
            for (int q = 0; q < 4; ++q) acc[mt][nt][q] = 0.f;

    int ar = tid >> 1, ac = (tid & 1) * 2;
    int br = tid >> 2, bc = tid & 3;
    const __half* Xsrc = d_Xh + (size_t)(m0 + ar) * KP + ac * 8;
    const __half* Wsrc = Wh   + (size_t)(n0 + br) * KP + bc * 8;
    uint32_t aBase = smem_u32(&Asm[0][0]);
    uint32_t bBase = smem_u32(&Bsm[0][0]);
    const uint32_t aBuf = 128 * 40 * 2, bBuf = 64 * 40 * 2;
    uint32_t aDst = aBase + (ar * 40 + ac * 8) * 2;
    uint32_t bDst = bBase + (br * 40 + bc * 8) * 2;

    const int NT = KP / 32;

    auto issue = [&](int it) {
        int buf = it & 1;
        const __half* as_ = Xsrc + it * 32;
        const __half* bs_ = Wsrc + it * 32;
        uint32_t ad = aDst + buf * aBuf;
        uint32_t bd = bDst + buf * bBuf;
        asm volatile(
            "cp.async.cg.shared.global [%0], [%1], 16;\n\t"
            "cp.async.cg.shared.global [%2], [%3], 16;\n\t"
            "cp.async.cg.shared.global [%4], [%5], 16;\n\t"
            "cp.async.commit_group;"
            :: "r"(ad), "l"(as_), "r"(ad + 16), "l"(as_ + 8), "r"(bd), "l"(bs_)
            : "memory");
    };

    uint32_t aRow[2], bRow[2];
    #pragma unroll
    for (int mt = 0; mt < 2; ++mt)
        aRow[mt] = ((warpM + mt * 16 + (lane & 15)) * 40 + ((lane >> 4) * 8)) * 2;
    #pragma unroll
    for (int p2 = 0; p2 < 2; ++p2)
        bRow[p2] = ((warpN + p2 * 16 + ((lane & 16) ? 8 : 0) + (lane & 7)) * 40
                    + ((lane & 8) ? 8 : 0)) * 2;

    issue(0);
    issue(1);

    for (int it = 0; it < NT; ++it) {
        if (it < NT - 1) asm volatile("cp.async.wait_group 1;" ::: "memory");
        else             asm volatile("cp.async.wait_group 0;" ::: "memory");
        __syncthreads();
        int buf = it & 1;
        uint32_t aB = aBase + buf * aBuf;
        uint32_t bB = bBase + buf * bBuf;
        #pragma unroll
        for (int kk = 0; kk < 32; kk += 16) {
            uint32_t a[2][4], b[2][4];
            #pragma unroll
            for (int mt = 0; mt < 2; ++mt)
                asm volatile("ldmatrix.sync.aligned.m8n8.x4.shared.b16 {%0,%1,%2,%3}, [%4];"
                             : "=r"(a[mt][0]), "=r"(a[mt][1]), "=r"(a[mt][2]), "=r"(a[mt][3])
                             : "r"(aB + aRow[mt] + kk * 2));
            #pragma unroll
            for (int p2 = 0; p2 < 2; ++p2)
                asm volatile("ldmatrix.sync.aligned.m8n8.x4.shared.b16 {%0,%1,%2,%3}, [%4];"
                             : "=r"(b[p2][0]), "=r"(b[p2][1]), "=r"(b[p2][2]), "=r"(b[p2][3])
                             : "r"(bB + bRow[p2] + kk * 2));
            #pragma unroll
            for (int mt = 0; mt < 2; ++mt)
                #pragma unroll
                for (int nt = 0; nt < 4; ++nt) {
                    uint32_t b0 = b[nt >> 1][(nt & 1) * 2];
                    uint32_t b1 = b[nt >> 1][(nt & 1) * 2 + 1];
                    asm volatile(
                        "mma.sync.aligned.m16n8k16.row.col.f32.f16.f16.f32 "
                        "{%0,%1,%2,%3}, {%4,%5,%6,%7}, {%8,%9}, {%0,%1,%2,%3};"
                        : "+f"(acc[mt][nt][0]), "+f"(acc[mt][nt][1]),
                          "+f"(acc[mt][nt][2]), "+f"(acc[mt][nt][3])
                        : "r"(a[mt][0]), "r"(a[mt][1]), "r"(a[mt][2]), "r"(a[mt][3]),
                          "r"(b0), "r"(b1));
                }
        }
        __syncthreads();
        if (it + 2 < NT) issue(it + 2);
    }

    #pragma unroll
    for (int mt = 0; mt < 2; ++mt) {
        #pragma unroll
        for (int hf = 0; hf < 2; ++hf) {
            int m = m0 + warpM + mt * 16 + gr + hf * 8;
            float* Orow = O + (size_t)m * G3;
            #pragma unroll
            for (int nt = 0; nt < 4; ++nt) {
                int col = n0 + warpN + nt * 8 + 2 * t4;
                if (col < G3) {
                    float v0 = acc[mt][nt][hf * 2 + 0] + bias[col];
                    float v1 = acc[mt][nt][hf * 2 + 1] + bias[col + 1];
                    *reinterpret_cast<float2*>(Orow + col) = make_float2(v0, v1);
                }
            }
        }
    }
}

// ---------------- persistent bidirectional GRU scan (R10: 16 warps, 2 tiles/warp) --------
__device__ __forceinline__ float sigm(float x) { return 1.f / (1.f + __expf(-x)); }
__device__ __forceinline__ float fast_tanh(float x) {
    float y; asm("tanh.approx.f32 %0, %1;" : "=f"(y) : "f"(x)); return y;
}

__global__ void __launch_bounds__(512, 1)
scan_kernel(const float* __restrict__ bhh_f, const float* __restrict__ bhh_b) {
    __shared__ __align__(8) float2 ghb2[JPAD];
    __shared__ __align__(4) __half h_s[2][KPAD2];

    int bb  = blockIdx.x;
    int dir = bb >> 6;
    int p   = bb & 63;
    int b0  = 2 * p, b1 = b0 + 1;
    const float* gi  = dir ? d_gi_b : d_gi_f;
    const float* bhh = dir ? bhh_b : bhh_f;
    const __half* Wd = d_Whh_h[dir];
    int tid = threadIdx.x;
    int wid = tid >> 5, lane = tid & 31;
    int g = lane >> 2, tig = lane & 3;

    for (int i = tid; i < 2 * KPAD2; i += 512)
        reinterpret_cast<__half*>(h_s)[i] = __float2half(0.f);

    const int t1 = wid;
    const int t2 = 16 + wid;
    const bool has2 = (t2 < MTILES);

    uint32_t A1[10][4], A2[10][4];
    {
        const __half* r0 = Wd + (size_t)(t1 * 16 + g) * KPAD2;
        const __half* r8 = r0 + 8 * KPAD2;
        #pragma unroll
        for (int kt = 0; kt < 10; ++kt) {
            int k0 = kt * 16 + tig * 2;
            A1[kt][0] = *reinterpret_cast<const uint32_t*>(r0 + k0);
            A1[kt][1] = *reinterpret_cast<const uint32_t*>(r8 + k0);
            A1[kt][2] = *reinterpret_cast<const uint32_t*>(r0 + k0 + 8);
            A1[kt][3] = *reinterpret_cast<const uint32_t*>(r8 + k0 + 8);
        }
        if (has2) {
            const __half* s0 = Wd + (size_t)(t2 * 16 + g) * KPAD2;
            const __half* s8 = s0 + 8 * KPAD2;
            #pragma unroll
            for (int kt = 0; kt < 10; ++kt) {
                int k0 = kt * 16 + tig * 2;
                A2[kt][0] = *reinterpret_cast<const uint32_t*>(s0 + k0);
                A2[kt][1] = *reinterpret_cast<const uint32_t*>(s8 + k0);
                A2[kt][2] = *reinterpret_cast<const uint32_t*>(s0 + k0 + 8);
                A2[kt][3] = *reinterpret_cast<const uint32_t*>(s8 + k0 + 8);
            }
        }
    }

    float cb1a, cb1b, cb2a = 0.f, cb2b = 0.f;
    {
        int m = t1 * 16 + g;
        cb1a = (m < G3) ? bhh[m] : 0.f;
        cb1b = (m + 8 < G3) ? bhh[m + 8] : 0.f;
        if (has2) {
            int m2 = t2 * 16 + g;
            cb2a = (m2 < G3) ? bhh[m2] : 0.f;
            cb2b = (m2 + 8 < G3) ? bhh[m2 + 8] : 0.f;
        }
    }

    const int e = tid;
    const bool ge = (e < 2 * HH);
    const int row = (e < HH) ? 0 : 1;
    const int jj  = e - row * HH;
    const size_t rowbase = (size_t)(row ? b1 : b0) * TT;

    __syncthreads();

    float g_r = 0.f, g_z = 0.f, g_n = 0.f;
    if (ge) {
        int t0 = dir ? (TT - 1) : 0;
        size_t gb = (rowbase + t0) * G3 + jj;
        g_r = gi[gb]; g_z = gi[gb + HH]; g_n = gi[gb + 2 * HH];
    }

    for (int s = 0; s < TT; ++s) {
        int t = dir ? (TT - 1 - s) : s;
        float nr = 0.f, nz = 0.f, nn = 0.f;
        if (ge && s + 1 < TT) {
            int tn = dir ? (TT - 2 - s) : (s + 1);
            size_t gb = (rowbase + tn) * G3 + jj;
            nr = gi[gb]; nz = gi[gb + HH]; nn = gi[gb + 2 * HH];
        }

        {
            float d1a[4] = {cb1a, cb1a, cb1b, cb1b};
            float d1b[4] = {0.f, 0.f, 0.f, 0.f};
            float d2a[4] = {cb2a, cb2a, cb2b, cb2b};
            float d2b[4] = {0.f, 0.f, 0.f, 0.f};
            uint32_t Bv[10][2];
            #pragma unroll
            for (int kt = 0; kt < 10; ++kt) {
                Bv[kt][0] = 0; Bv[kt][1] = 0;
                if (g < 2) {
                    const __half* hp = &h_s[g][kt * 16 + tig * 2];
                    Bv[kt][0] = *reinterpret_cast<const uint32_t*>(hp);
                    Bv[kt][1] = *reinterpret_cast<const uint32_t*>(hp + 8);
                }
            }
            #pragma unroll
            for (int kt = 0; kt < 10; kt += 2) {
                mma16816(d1a, A1[kt],     Bv[kt][0],     Bv[kt][1]);
                mma16816(d1b, A1[kt + 1], Bv[kt + 1][0], Bv[kt + 1][1]);
                if (has2) {
                    mma16816(d2a, A2[kt],     Bv[kt][0],     Bv[kt][1]);
                    mma16816(d2b, A2[kt + 1], Bv[kt + 1][0], Bv[kt + 1][1]);
                }
            }
            if (tig == 0) {
                int m = t1 * 16 + g;
                ghb2[m]     = make_float2(d1a[0] + d1b[0], d1a[1] + d1b[1]);
                ghb2[m + 8] = make_float2(d1a[2] + d1b[2], d1a[3] + d1b[3]);
                if (has2) {
                    int m2 = t2 * 16 + g;
                    ghb2[m2]     = make_float2(d2a[0] + d2b[0], d2a[1] + d2b[1]);
                    ghb2[m2 + 8] = make_float2(d2a[2] + d2b[2], d2a[3] + d2b[3]);
                }
            }
        }
        __syncthreads();

        if (ge) {
            const float* gb = reinterpret_cast<const float*>(ghb2);
            float hr = gb[jj * 2 + row];
            float hz = gb[(jj + HH) * 2 + row];
            float hn = gb[(jj + 2 * HH) * 2 + row];
            float rg = sigm(g_r + hr);
            float zg = sigm(g_z + hz);
            float ng = fast_tanh(g_n + rg * hn);
            float hp = __half2float(h_s[row][jj]);
            float hv = (1.f - zg) * ng + zg * hp;
            h_s[row][jj] = __float2half(hv);
            d_seq[(rowbase + t) * (2 * HH) + dir * HH + jj] = hv;
        }
        __syncthreads();
        g_r = nr; g_z = nz; g_n = nn;
    }
    if (ge) {
        float hv = __half2float(h_s[row][jj]);
        d_hidden[(size_t)(row ? b1 : b0) * (2 * HH) + dir * HH + jj] = hv;
    }
}

// ---------------- context ----------------
__global__ void ctx_kernel(const float* __restrict__ Wattn) {
    int bk = blockIdx.x;
    int b = bk / KK, k = bk - b * KK;
    __shared__ float hs[2 * HH];
    int tid = threadIdx.x;
    if (tid < 2 * HH) hs[tid] = d_hidden[b * 2 * HH + tid];
    __syncthreads();
    if (tid < 2 * HH) {
        float acc = d_bias2[k * 2 * HH + tid];
        const float* w = Wattn + ((size_t)k * (CC + 2 * HH) + CC) * (2 * HH) + tid;
        #pragma unroll 4
        for (int c = 0; c < 2 * HH; ++c) acc += hs[c] * w[(size_t)c * (2 * HH)];
        d_context[((size_t)b * KK + k) * (2 * HH) + tid] = tanhf(acc);
    }
}

// ---------------- energy -> softmax(t) -> pooled ----------------
__global__ void pool_kernel() {
    int b = blockIdx.x;
    __shared__ float ctx[KK][2 * HH];
    __shared__ float en[TT][KK];
    int tid = threadIdx.x;              // 512
    int w = tid >> 5, lane = tid & 31;
    for (int i = tid; i < KK * 2 * HH; i += 512)
        ctx[i / (2 * HH)][i % (2 * HH)] = d_context[(size_t)b * KK * 2 * HH + i];
    __syncthreads();
    for (int t = w; t < TT; t += 16) {
        const float* srow = d_seq + ((size_t)b * TT + t) * (2 * HH);
        float pk[KK] = {0, 0, 0, 0, 0, 0};
        for (int d = lane; d < 2 * HH; d += 32) {
            float s = srow[d];
            #pragma unroll
            for (int k = 0; k < KK; ++k) pk[k] = fmaf(s, ctx[k][d], pk[k]);
        }
        #pragma unroll
        for (int k = 0; k < KK; ++k) {
            float v = pk[k];
            for (int off = 16; off; off >>= 1) v += __shfl_xor_sync(~0u, v, off);
            if (lane == 0) en[t][k] = v;
        }
    }
    __syncthreads();
    if (w < KK) {
        float mx = -1e30f;
        for (int t = lane; t < TT; t += 32) mx = fmaxf(mx, en[t][w]);
        for (int off = 16; off; off >>= 1) mx = fmaxf(mx, __shfl_xor_sync(~0u, mx, off));
        float sum = 0.f;
        for (int t = lane; t < TT; t += 32) { float e2 = __expf(en[t][w] - mx); en[t][w] = e2; sum += e2; }
        for (int off = 16; off; off >>= 1) sum += __shfl_xor_sync(~0u, sum, off);
        float inv = 1.f / sum;
        for (int t = lane; t < TT; t += 32) en[t][w] *= inv;
    }
    __syncthreads();
    // pooled: float2 per thread (150 threads), t unrolled for MLP
    if (tid < HH) {
        int d = tid * 2;
        float acc0[KK] = {0, 0, 0, 0, 0, 0};
        float acc1[KK] = {0, 0, 0, 0, 0, 0};
        const float* sp = d_seq + (size_t)b * TT * (2 * HH) + d;
        #pragma unroll 8
        for (int t = 0; t < TT; ++t) {
            float2 s = *reinterpret_cast<const float2*>(sp + (size_t)t * (2 * HH));
            #pragma unroll
            for (int k = 0; k < KK; ++k) {
                float pr = en[t][k];
                acc0[k] = fmaf(s.x, pr, acc0[k]);
                acc1[k] = fmaf(s.y, pr, acc1[k]);
            }
        }
        #pragma unroll
        for (int k = 0; k < KK; ++k) {
            float* dst = d_pooled + ((size_t)b * KK + k) * (2 * HH) + d;
            dst[0] = acc0[k];
            dst[1] = acc1[k];
        }
    }
}

// ---------------- topic -> logits -> softmax ----------------
__global__ void topic_kernel(const float* __restrict__ Wtop, const float* __restrict__ btop,
                             const float* __restrict__ Wout, const float* __restrict__ bout,
                             float* __restrict__ out) {
    int b = blockIdx.x;
    __shared__ float ps[KK * 2 * HH];
    __shared__ float feats[KK * THD];
    __shared__ float lg[CLS];
    int tid = threadIdx.x;
    for (int i = tid; i < KK * 2 * HH; i += 128) ps[i] = d_pooled[(size_t)b * KK * 2 * HH + i];
    __syncthreads();
    if (tid < KK * THD) {
        int k = tid / THD, th = tid - k * THD;
        float acc = btop[tid];
        const float* wp = Wtop + (size_t)k * (2 * HH) * THD + th;
        #pragma unroll 4
        for (int d = 0; d < 2 * HH; ++d) acc += ps[k * 2 * HH + d] * wp[d * THD];
        feats[tid] = fmaxf(acc, 0.f);
    }
    __syncthreads();
    if (tid < CLS) {
        float acc = bout[tid];
        for (int e2 = 0; e2 < KK * THD; ++e2) acc += feats[e2] * Wout[e2 * CLS + tid];
        lg[tid] = acc;
    }
    __syncthreads();
    if (tid < CLS) {
        float mx = lg[0];
        #pragma unroll
        for (int c = 1; c < CLS; ++c) mx = fmaxf(mx, lg[c]);
        float sum = 0.f;
        #pragma unroll
        for (int c = 0; c < CLS; ++c) sum += __expf(lg[c] - mx);
        out[b * CLS + tid] = __expf(lg[tid] - mx) / sum;
    }
}

// ---------------- orthogonality regularizer ----------------
__global__ void reg_partial_kernel() {
    int b = blockIdx.x;
    __shared__ float cs[KK * 2 * HH];
    __shared__ float D[KK * KK];
    int tid = threadIdx.x;
    int w = tid >> 5, lane = tid & 31;
    for (int i = tid; i < KK * 2 * HH; i += 256) cs[i] = d_context[(size_t)b * KK * 2 * HH + i];
    __syncthreads();
    for (int p2 = w; p2 < KK * KK; p2 += 8) {
        int k = p2 / KK, j = p2 - k * KK;
        float v = 0.f;
        for (int d = lane; d < 2 * HH; d += 32) v += cs[k * 2 * HH + d] * cs[j * 2 * HH + d];
        for (int off = 16; off; off >>= 1) v += __shfl_xor_sync(~0u, v, off);
        if (lane == 0) D[p2] = v;
    }
    __syncthreads();
    if (tid == 0) {
        float nk[KK];
        #pragma unroll
        for (int k = 0; k < KK; ++k) nk[k] = fmaxf(sqrtf(D[k * KK + k]), 1e-12f);
        float S = 0.f;
        for (int k = 0; k < KK; ++k)
            for (int j = 0; j < KK; ++j) {
                float g = D[k * KK + j] / (nk[k] * nk[j]) - (k == j ? 1.f : 0.f);
                S += g * g;
            }
        d_regpart[b] = sqrtf(S);
    }
}

__global__ void reg_final_kernel(float* __restrict__ regout) {
    __shared__ float s[BB];
    int tid = threadIdx.x;
    s[tid] = d_regpart[tid];
    __syncthreads();
    for (int off = 64; off; off >>= 1) {
        if (tid < off) s[tid] += s[tid + off];
        __syncthreads();
    }
    if (tid == 0) *regout = s[0] / (float)BB;
}

// ---------------- launch ------------------------------------------------------------------
extern "C" void kernel_launch(void* const* d_in, const int* in_sizes, int n_in,
                              void* d_out, int out_size) {
    const float* x      = (const float*)d_in[0];
    const float* Wih_f  = (const float*)d_in[1];
    const float* Whh_f  = (const float*)d_in[2];
    const float* bih_f  = (const float*)d_in[3];
    const float* bhh_f  = (const float*)d_in[4];
    const float* Wih_b  = (const float*)d_in[5];
    const float* Whh_b  = (const float*)d_in[6];
    const float* bih_b  = (const float*)d_in[7];
    const float* bhh_b  = (const float*)d_in[8];
    const float* attn_c = (const float*)d_in[9];
    const float* Wattn  = (const float*)d_in[10];
    const float* battn  = (const float*)d_in[11];
    const float* Wtop   = (const float*)d_in[12];
    const float* btop   = (const float*)d_in[13];
    const float* Wout   = (const float*)d_in[14];
    const float* bout   = (const float*)d_in[15];
    float* out = (float*)d_out;

    prep_kernel<<<(2 * JPAD * KPAD2 + 255) / 256, 256>>>(Whh_f, Whh_b);
    const int npair = MM * (KP / 2) + 2 * 512 * (KP / 2);
    convert_kernel<<<(npair + 255) / 256, 256>>>(x, Wih_f, Wih_b);
    bias2_kernel<<<KK, 320>>>(attn_c, Wattn, battn);

    gemm_gi<<<dim3(8, 512, 2), 256>>>(bih_f, bih_b);

    scan_kernel<<<128, 512>>>(bhh_f, bhh_b);

    ctx_kernel<<<BB * KK, 320>>>(Wattn);
    pool_kernel<<<BB, 512>>>();
    topic_kernel<<<BB, 128>>>(Wtop, btop, Wout, bout, out);
    if (out_size > BB * CLS) {
        reg_partial_kernel<<<BB, 256>>>();
        reg_final_kernel<<<1, BB>>>(out + BB * CLS);
    }
}

// round 15
// speedup vs baseline: 1.3022x; 1.0272x over previous
#include <cuda_runtime.h>
#include <cuda_fp16.h>
#include <cstdint>

#define BB   128
#define TT   512
#define II   300
#define HH   150
#define G3   450
#define KK   6
#define CC   300
#define THD  20
#define CLS  5

#define KP   320
#define MM   (BB * TT)

#define JPAD  464
#define KPAD2 160
#define MTILES 29

// ---------------- scratch ----------------
__device__ float d_gi_f[(size_t)MM * G3];
__device__ float d_gi_b[(size_t)MM * G3];
__device__ float d_seq [(size_t)MM * 2 * HH];
__device__ float d_hidden[BB * 2 * HH];
__device__ __half d_Whh_h[2][JPAD * KPAD2];
__device__ __half d_Xh[(size_t)MM * KP];
__device__ __half d_Wh[2][512 * KP];
__device__ float d_bias2[KK * 2 * HH];
__device__ float d_context[BB * KK * 2 * HH];
__device__ float d_pooled [BB * KK * 2 * HH];
__device__ float d_regpart[BB];

__device__ __forceinline__ uint32_t smem_u32(const void* p) {
    uint32_t r;
    asm("{ .reg .u64 t; cvta.to.shared.u64 t, %1; cvt.u32.u64 %0, t; }" : "=r"(r) : "l"(p));
    return r;
}

__device__ __forceinline__ void mma16816(float* d, const uint32_t* a, uint32_t b0, uint32_t b1) {
    asm volatile(
        "mma.sync.aligned.m16n8k16.row.col.f32.f16.f16.f32 "
        "{%0,%1,%2,%3}, {%4,%5,%6,%7}, {%8,%9}, {%0,%1,%2,%3};"
        : "+f"(d[0]), "+f"(d[1]), "+f"(d[2]), "+f"(d[3])
        : "r"(a[0]), "r"(a[1]), "r"(a[2]), "r"(a[3]), "r"(b0), "r"(b1));
}

// ---------------- prep: Whh -> half [JPAD][KPAD2], zero padded ----------------
__global__ void prep_kernel(const float* __restrict__ Whh_f, const float* __restrict__ Whh_b) {
    int idx = blockIdx.x * blockDim.x + threadIdx.x;
    int tot = JPAD * KPAD2;
    if (idx < 2 * tot) {
        int d = idx / tot;
        int r = idx - d * tot;
        int j = r / KPAD2, i = r - j * KPAD2;
        const float* W = d ? Whh_b : Whh_f;
        d_Whh_h[d][r] = (j < G3 && i < HH) ? __float2half(W[j * HH + i]) : __float2half(0.f);
    }
}

// ---------------- convert X, Wih -> padded half ----------------
__global__ void convert_kernel(const float* __restrict__ X,
                               const float* __restrict__ Wf, const float* __restrict__ Wb) {
    int idx = blockIdx.x * blockDim.x + threadIdx.x;
    const int totX = MM * (KP / 2);
    if (idx < totX) {
        int m = idx / (KP / 2), kp = idx - m * (KP / 2);
        int k = kp * 2;
        float a = (k < II)     ? X[(size_t)m * II + k]     : 0.f;
        float b = (k + 1 < II) ? X[(size_t)m * II + k + 1] : 0.f;
        reinterpret_cast<__half2*>(d_Xh)[idx] = __floats2half2_rn(a, b);
    } else {
        int r = idx - totX;
        const int totW = 512 * (KP / 2);
        if (r < 2 * totW) {
            int d = r / totW;
            int rr = r - d * totW;
            int n = rr / (KP / 2), kp = rr - n * (KP / 2);
            int k = kp * 2;
            const float* W = d ? Wb : Wf;
            float a = (n < G3 && k < II)     ? W[(size_t)n * II + k]     : 0.f;
            float b = (n < G3 && k + 1 < II) ? W[(size_t)n * II + k + 1] : 0.f;
            reinterpret_cast<__half2*>(d_Wh[d])[rr] = __floats2half2_rn(a, b);
        }
    }
}

// ---------------- bias2 ----------------
__global__ void bias2_kernel(const float* __restrict__ ac, const float* __restrict__ Wattn,
                             const float* __restrict__ battn) {
    int k = blockIdx.x;
    __shared__ float as[CC];
    int tid = threadIdx.x;
    if (tid < CC) as[tid] = ac[k * CC + tid];
    __syncthreads();
    if (tid < 2 * HH) {
        float acc = battn[k * 2 * HH + tid];
        const float* w = Wattn + (size_t)k * (CC + 2 * HH) * (2 * HH) + tid;
        #pragma unroll 4
        for (int c = 0; c < CC; ++c) acc += as[c] * w[(size_t)c * (2 * HH)];
        d_bias2[k * 2 * HH + tid] = acc;
    }
}

// ---------------- gi GEMM: 3-stage cp.async pipeline, ONE barrier per iter ----------------
__global__ void __launch_bounds__(256, 2)
gemm_gi(const float* __restrict__ bf, const float* __restrict__ bb) {
    __shared__ __align__(16) __half Asm[3][128 * 40];
    __shared__ __align__(16) __half Bsm[3][64 * 40];
    int which = blockIdx.z;
    const __half* Wh  = d_Wh[which];
    const float* bias = which ? bb : bf;
    float* O          = which ? d_gi_b : d_gi_f;

    int m0 = blockIdx.y * 128;
    int n0 = blockIdx.x * 64;
    int tid = threadIdx.x;
    int wid = tid >> 5, lane = tid & 31;
    int warpM = (wid & 3) * 32;
    int warpN = (wid >> 2) * 32;
    int gr = lane >> 2, t4 = lane & 3;

    float acc[2][4][4];
    #pragma unroll
    for (int mt = 0; mt < 2; ++mt)
        #pragma unroll
        for (int nt = 0; nt < 4; ++nt)
            #pragma unroll
            for (int q = 0; q < 4; ++q) acc[mt][nt][q] = 0.f;

    int ar = tid >> 1, ac = (tid & 1) * 2;
    int br = tid >> 2, bc = tid & 3;
    const __half* Xsrc = d_Xh + (size_t)(m0 + ar) * KP + ac * 8;
    const __half* Wsrc = Wh   + (size_t)(n0 + br) * KP + bc * 8;
    uint32_t aBase = smem_u32(&Asm[0][0]);
    uint32_t bBase = smem_u32(&Bsm[0][0]);
    const uint32_t aBuf = 128 * 40 * 2, bBuf = 64 * 40 * 2;
    uint32_t aDst = aBase + (ar * 40 + ac * 8) * 2;
    uint32_t bDst = bBase + (br * 40 + bc * 8) * 2;

    const int NT = KP / 32;   // 10

    auto issue = [&](int it) {
        int buf = it % 3;
        const __half* as_ = Xsrc + it * 32;
        const __half* bs_ = Wsrc + it * 32;
        uint32_t ad = aDst + buf * aBuf;
        uint32_t bd = bDst + buf * bBuf;
        asm volatile(
            "cp.async.cg.shared.global [%0], [%1], 16;\n\t"
            "cp.async.cg.shared.global [%2], [%3], 16;\n\t"
            "cp.async.cg.shared.global [%4], [%5], 16;\n\t"
            "cp.async.commit_group;"
            :: "r"(ad), "l"(as_), "r"(ad + 16), "l"(as_ + 8), "r"(bd), "l"(bs_)
            : "memory");
    };

    uint32_t aRow[2], bRow[2];
    #pragma unroll
    for (int mt = 0; mt < 2; ++mt)
        aRow[mt] = ((warpM + mt * 16 + (lane & 15)) * 40 + ((lane >> 4) * 8)) * 2;
    #pragma unroll
    for (int p2 = 0; p2 < 2; ++p2)
        bRow[p2] = ((warpN + p2 * 16 + ((lane & 16) ? 8 : 0) + (lane & 7)) * 40
                    + ((lane & 8) ? 8 : 0)) * 2;

    issue(0);
    issue(1);

    for (int it = 0; it < NT; ++it) {
        // drain so buffer it%3 is complete; keep at most 1 group (iter it+1) in flight
        if (it < NT - 1) asm volatile("cp.async.wait_group 1;" ::: "memory");
        else             asm volatile("cp.async.wait_group 0;" ::: "memory");
        __syncthreads();   // also separates iter it-1's reads from the issue below
        if (it + 2 < NT) issue(it + 2);   // writes buffer (it+2)%3 == (it-1)%3, reads done

        int buf = it % 3;
        uint32_t aB = aBase + buf * aBuf;
        uint32_t bB = bBase + buf * bBuf;
        #pragma unroll
        for (int kk = 0; kk < 32; kk += 16) {
            uint32_t a[2][4], b[2][4];
            #pragma unroll
            for (int mt = 0; mt < 2; ++mt)
                asm volatile("ldmatrix.sync.aligned.m8n8.x4.shared.b16 {%0,%1,%2,%3}, [%4];"
                             : "=r"(a[mt][0]), "=r"(a[mt][1]), "=r"(a[mt][2]), "=r"(a[mt][3])
                             : "r"(aB + aRow[mt] + kk * 2));
            #pragma unroll
            for (int p2 = 0; p2 < 2; ++p2)
                asm volatile("ldmatrix.sync.aligned.m8n8.x4.shared.b16 {%0,%1,%2,%3}, [%4];"
                             : "=r"(b[p2][0]), "=r"(b[p2][1]), "=r"(b[p2][2]), "=r"(b[p2][3])
                             : "r"(bB + bRow[p2] + kk * 2));
            #pragma unroll
            for (int mt = 0; mt < 2; ++mt)
                #pragma unroll
                for (int nt = 0; nt < 4; ++nt) {
                    uint32_t b0 = b[nt >> 1][(nt & 1) * 2];
                    uint32_t b1 = b[nt >> 1][(nt & 1) * 2 + 1];
                    asm volatile(
                        "mma.sync.aligned.m16n8k16.row.col.f32.f16.f16.f32 "
                        "{%0,%1,%2,%3}, {%4,%5,%6,%7}, {%8,%9}, {%0,%1,%2,%3};"
                        : "+f"(acc[mt][nt][0]), "+f"(acc[mt][nt][1]),
                          "+f"(acc[mt][nt][2]), "+f"(acc[mt][nt][3])
                        : "r"(a[mt][0]), "r"(a[mt][1]), "r"(a[mt][2]), "r"(a[mt][3]),
                          "r"(b0), "r"(b1));
                }
        }
    }

    #pragma unroll
    for (int mt = 0; mt < 2; ++mt) {
        #pragma unroll
        for (int hf = 0; hf < 2; ++hf) {
            int m = m0 + warpM + mt * 16 + gr + hf * 8;
            float* Orow = O + (size_t)m * G3;
            #pragma unroll
            for (int nt = 0; nt < 4; ++nt) {
                int col = n0 + warpN + nt * 8 + 2 * t4;
                if (col < G3) {
                    float v0 = acc[mt][nt][hf * 2 + 0] + bias[col];
                    float v1 = acc[mt][nt][hf * 2 + 1] + bias[col + 1];
                    *reinterpret_cast<float2*>(Orow + col) = make_float2(v0, v1);
                }
            }
        }
    }
}

// ---------------- persistent bidirectional GRU scan (R10/R14 proven version) -------------
__device__ __forceinline__ float sigm(float x) { return 1.f / (1.f + __expf(-x)); }
__device__ __forceinline__ float fast_tanh(float x) {
    float y; asm("tanh.approx.f32 %0, %1;" : "=f"(y) : "f"(x)); return y;
}

__global__ void __launch_bounds__(512, 1)
scan_kernel(const float* __restrict__ bhh_f, const float* __restrict__ bhh_b) {
    __shared__ __align__(8) float2 ghb2[JPAD];
    __shared__ __align__(4) __half h_s[2][KPAD2];

    int bb  = blockIdx.x;
    int dir = bb >> 6;
    int p   = bb & 63;
    int b0  = 2 * p, b1 = b0 + 1;
    const float* gi  = dir ? d_gi_b : d_gi_f;
    const float* bhh = dir ? bhh_b : bhh_f;
    const __half* Wd = d_Whh_h[dir];
    int tid = threadIdx.x;
    int wid = tid >> 5, lane = tid & 31;
    int g = lane >> 2, tig = lane & 3;

    for (int i = tid; i < 2 * KPAD2; i += 512)
        reinterpret_cast<__half*>(h_s)[i] = __float2half(0.f);

    const int t1 = wid;
    const int t2 = 16 + wid;
    const bool has2 = (t2 < MTILES);

    uint32_t A1[10][4], A2[10][4];
    {
        const __half* r0 = Wd + (size_t)(t1 * 16 + g) * KPAD2;
        const __half* r8 = r0 + 8 * KPAD2;
        #pragma unroll
        for (int kt = 0; kt < 10; ++kt) {
            int k0 = kt * 16 + tig * 2;
            A1[kt][0] = *reinterpret_cast<const uint32_t*>(r0 + k0);
            A1[kt][1] = *reinterpret_cast<const uint32_t*>(r8 + k0);
            A1[kt][2] = *reinterpret_cast<const uint32_t*>(r0 + k0 + 8);
            A1[kt][3] = *reinterpret_cast<const uint32_t*>(r8 + k0 + 8);
        }
        if (has2) {
            const __half* s0 = Wd + (size_t)(t2 * 16 + g) * KPAD2;
            const __half* s8 = s0 + 8 * KPAD2;
            #pragma unroll
            for (int kt = 0; kt < 10; ++kt) {
                int k0 = kt * 16 + tig * 2;
                A2[kt][0] = *reinterpret_cast<const uint32_t*>(s0 + k0);
                A2[kt][1] = *reinterpret_cast<const uint32_t*>(s8 + k0);
                A2[kt][2] = *reinterpret_cast<const uint32_t*>(s0 + k0 + 8);
                A2[kt][3] = *reinterpret_cast<const uint32_t*>(s8 + k0 + 8);
            }
        }
    }

    float cb1a, cb1b, cb2a = 0.f, cb2b = 0.f;
    {
        int m = t1 * 16 + g;
        cb1a = (m < G3) ? bhh[m] : 0.f;
        cb1b = (m + 8 < G3) ? bhh[m + 8] : 0.f;
        if (has2) {
            int m2 = t2 * 16 + g;
            cb2a = (m2 < G3) ? bhh[m2] : 0.f;
            cb2b = (m2 + 8 < G3) ? bhh[m2 + 8] : 0.f;
        }
    }

    const int e = tid;
    const bool ge = (e < 2 * HH);
    const int row = (e < HH) ? 0 : 1;
    const int jj  = e - row * HH;
    const size_t rowbase = (size_t)(row ? b1 : b0) * TT;

    __syncthreads();

    float g_r = 0.f, g_z = 0.f, g_n = 0.f;
    if (ge) {
        int t0 = dir ? (TT - 1) : 0;
        size_t gb = (rowbase + t0) * G3 + jj;
        g_r = gi[gb]; g_z = gi[gb + HH]; g_n = gi[gb + 2 * HH];
    }

    for (int s = 0; s < TT; ++s) {
        int t = dir ? (TT - 1 - s) : s;
        float nr = 0.f, nz = 0.f, nn = 0.f;
        if (ge && s + 1 < TT) {
            int tn = dir ? (TT - 2 - s) : (s + 1);
            size_t gb = (rowbase + tn) * G3 + jj;
            nr = gi[gb]; nz = gi[gb + HH]; nn = gi[gb + 2 * HH];
        }

        {
            float d1a[4] = {cb1a, cb1a, cb1b, cb1b};
            float d1b[4] = {0.f, 0.f, 0.f, 0.f};
            float d2a[4] = {cb2a, cb2a, cb2b, cb2b};
            float d2b[4] = {0.f, 0.f, 0.f, 0.f};
            uint32_t Bv[10][2];
            #pragma unroll
            for (int kt = 0; kt < 10; ++kt) {
                Bv[kt][0] = 0; Bv[kt][1] = 0;
                if (g < 2) {
                    const __half* hp = &h_s[g][kt * 16 + tig * 2];
                    Bv[kt][0] = *reinterpret_cast<const uint32_t*>(hp);
                    Bv[kt][1] = *reinterpret_cast<const uint32_t*>(hp + 8);
                }
            }
            #pragma unroll
            for (int kt = 0; kt < 10; kt += 2) {
                mma16816(d1a, A1[kt],     Bv[kt][0],     Bv[kt][1]);
                mma16816(d1b, A1[kt + 1], Bv[kt + 1][0], Bv[kt + 1][1]);
                if (has2) {
                    mma16816(d2a, A2[kt],     Bv[kt][0],     Bv[kt][1]);
                    mma16816(d2b, A2[kt + 1], Bv[kt + 1][0], Bv[kt + 1][1]);
                }
            }
            if (tig == 0) {
                int m = t1 * 16 + g;
                ghb2[m]     = make_float2(d1a[0] + d1b[0], d1a[1] + d1b[1]);
                ghb2[m + 8] = make_float2(d1a[2] + d1b[2], d1a[3] + d1b[3]);
                if (has2) {
                    int m2 = t2 * 16 + g;
                    ghb2[m2]     = make_float2(d2a[0] + d2b[0], d2a[1] + d2b[1]);
                    ghb2[m2 + 8] = make_float2(d2a[2] + d2b[2], d2a[3] + d2b[3]);
                }
            }
        }
        __syncthreads();

        if (ge) {
            const float* gb = reinterpret_cast<const float*>(ghb2);
            float hr = gb[jj * 2 + row];
            float hz = gb[(jj + HH) * 2 + row];
            float hn = gb[(jj + 2 * HH) * 2 + row];
            float rg = sigm(g_r + hr);
            float zg = sigm(g_z + hz);
            float ng = fast_tanh(g_n + rg * hn);
            float hp = __half2float(h_s[row][jj]);
            float hv = (1.f - zg) * ng + zg * hp;
            h_s[row][jj] = __float2half(hv);
            d_seq[(rowbase + t) * (2 * HH) + dir * HH + jj] = hv;
        }
        __syncthreads();
        g_r = nr; g_z = nz; g_n = nn;
    }
    if (ge) {
        float hv = __half2float(h_s[row][jj]);
        d_hidden[(size_t)(row ? b1 : b0) * (2 * HH) + dir * HH + jj] = hv;
    }
}

// ---------------- context ----------------
__global__ void ctx_kernel(const float* __restrict__ Wattn) {
    int bk = blockIdx.x;
    int b = bk / KK, k = bk - b * KK;
    __shared__ float hs[2 * HH];
    int tid = threadIdx.x;
    if (tid < 2 * HH) hs[tid] = d_hidden[b * 2 * HH + tid];
    __syncthreads();
    if (tid < 2 * HH) {
        float acc = d_bias2[k * 2 * HH + tid];
        const float* w = Wattn + ((size_t)k * (CC + 2 * HH) + CC) * (2 * HH) + tid;
        #pragma unroll 4
        for (int c = 0; c < 2 * HH; ++c) acc += hs[c] * w[(size_t)c * (2 * HH)];
        d_context[((size_t)b * KK + k) * (2 * HH) + tid] = tanhf(acc);
    }
}

// ---------------- energy -> softmax(t) -> pooled ----------------
__global__ void pool_kernel() {
    int b = blockIdx.x;
    __shared__ float ctx[KK][2 * HH];
    __shared__ float en[TT][KK];
    int tid = threadIdx.x;              // 512
    int w = tid >> 5, lane = tid & 31;
    for (int i = tid; i < KK * 2 * HH; i += 512)
        ctx[i / (2 * HH)][i % (2 * HH)] = d_context[(size_t)b * KK * 2 * HH + i];
    __syncthreads();
    for (int t = w; t < TT; t += 16) {
        const float* srow = d_seq + ((size_t)b * TT + t) * (2 * HH);
        float pk[KK] = {0, 0, 0, 0, 0, 0};
        for (int d = lane; d < 2 * HH; d += 32) {
            float s = srow[d];
            #pragma unroll
            for (int k = 0; k < KK; ++k) pk[k] = fmaf(s, ctx[k][d], pk[k]);
        }
        #pragma unroll
        for (int k = 0; k < KK; ++k) {
            float v = pk[k];
            for (int off = 16; off; off >>= 1) v += __shfl_xor_sync(~0u, v, off);
            if (lane == 0) en[t][k] = v;
        }
    }
    __syncthreads();
    if (w < KK) {
        float mx = -1e30f;
        for (int t = lane; t < TT; t += 32) mx = fmaxf(mx, en[t][w]);
        for (int off = 16; off; off >>= 1) mx = fmaxf(mx, __shfl_xor_sync(~0u, mx, off));
        float sum = 0.f;
        for (int t = lane; t < TT; t += 32) { float e2 = __expf(en[t][w] - mx); en[t][w] = e2; sum += e2; }
        for (int off = 16; off; off >>= 1) sum += __shfl_xor_sync(~0u, sum, off);
        float inv = 1.f / sum;
        for (int t = lane; t < TT; t += 32) en[t][w] *= inv;
    }
    __syncthreads();
    if (tid < HH) {
        int d = tid * 2;
        float acc0[KK] = {0, 0, 0, 0, 0, 0};
        float acc1[KK] = {0, 0, 0, 0, 0, 0};
        const float* sp = d_seq + (size_t)b * TT * (2 * HH) + d;
        #pragma unroll 8
        for (int t = 0; t < TT; ++t) {
            float2 s = *reinterpret_cast<const float2*>(sp + (size_t)t * (2 * HH));
            #pragma unroll
            for (int k = 0; k < KK; ++k) {
                float pr = en[t][k];
                acc0[k] = fmaf(s.x, pr, acc0[k]);
                acc1[k] = fmaf(s.y, pr, acc1[k]);
            }
        }
        #pragma unroll
        for (int k = 0; k < KK; ++k) {
            float* dst = d_pooled + ((size_t)b * KK + k) * (2 * HH) + d;
            dst[0] = acc0[k];
            dst[1] = acc1[k];
        }
    }
}

// ---------------- topic -> logits -> softmax ----------------
__global__ void topic_kernel(const float* __restrict__ Wtop, const float* __restrict__ btop,
                             const float* __restrict__ Wout, const float* __restrict__ bout,
                             float* __restrict__ out) {
    int b = blockIdx.x;
    __shared__ float ps[KK * 2 * HH];
    __shared__ float feats[KK * THD];
    __shared__ float lg[CLS];
    int tid = threadIdx.x;
    for (int i = tid; i < KK * 2 * HH; i += 128) ps[i] = d_pooled[(size_t)b * KK * 2 * HH + i];
    __syncthreads();
    if (tid < KK * THD) {
        int k = tid / THD, th = tid - k * THD;
        float acc = btop[tid];
        const float* wp = Wtop + (size_t)k * (2 * HH) * THD + th;
        #pragma unroll 4
        for (int d = 0; d < 2 * HH; ++d) acc += ps[k * 2 * HH + d] * wp[d * THD];
        feats[tid] = fmaxf(acc, 0.f);
    }
    __syncthreads();
    if (tid < CLS) {
        float acc = bout[tid];
        for (int e2 = 0; e2 < KK * THD; ++e2) acc += feats[e2] * Wout[e2 * CLS + tid];
        lg[tid] = acc;
    }
    __syncthreads();
    if (tid < CLS) {
        float mx = lg[0];
        #pragma unroll
        for (int c = 1; c < CLS; ++c) mx = fmaxf(mx, lg[c]);
        float sum = 0.f;
        #pragma unroll
        for (int c = 0; c < CLS; ++c) sum += __expf(lg[c] - mx);
        out[b * CLS + tid] = __expf(lg[tid] - mx) / sum;
    }
}

// ---------------- orthogonality regularizer ----------------
__global__ void reg_partial_kernel() {
    int b = blockIdx.x;
    __shared__ float cs[KK * 2 * HH];
    __shared__ float D[KK * KK];
    int tid = threadIdx.x;
    int w = tid >> 5, lane = tid & 31;
    for (int i = tid; i < KK * 2 * HH; i += 256) cs[i] = d_context[(size_t)b * KK * 2 * HH + i];
    __syncthreads();
    for (int p2 = w; p2 < KK * KK; p2 += 8) {
        int k = p2 / KK, j = p2 - k * KK;
        float v = 0.f;
        for (int d = lane; d < 2 * HH; d += 32) v += cs[k * 2 * HH + d] * cs[j * 2 * HH + d];
        for (int off = 16; off; off >>= 1) v += __shfl_xor_sync(~0u, v, off);
        if (lane == 0) D[p2] = v;
    }
    __syncthreads();
    if (tid == 0) {
        float nk[KK];
        #pragma unroll
        for (int k = 0; k < KK; ++k) nk[k] = fmaxf(sqrtf(D[k * KK + k]), 1e-12f);
        float S = 0.f;
        for (int k = 0; k < KK; ++k)
            for (int j = 0; j < KK; ++j) {
                float g = D[k * KK + j] / (nk[k] * nk[j]) - (k == j ? 1.f : 0.f);
                S += g * g;
            }
        d_regpart[b] = sqrtf(S);
    }
}

__global__ void reg_final_kernel(float* __restrict__ regout) {
    __shared__ float s[BB];
    int tid = threadIdx.x;
    s[tid] = d_regpart[tid];
    __syncthreads();
    for (int off = 64; off; off >>= 1) {
        if (tid < off) s[tid] += s[tid + off];
        __syncthreads();
    }
    if (tid == 0) *regout = s[0] / (float)BB;
}

// ---------------- launch ------------------------------------------------------------------
extern "C" void kernel_launch(void* const* d_in, const int* in_sizes, int n_in,
                              void* d_out, int out_size) {
    const float* x      = (const float*)d_in[0];
    const float* Wih_f  = (const float*)d_in[1];
    const float* Whh_f  = (const float*)d_in[2];
    const float* bih_f  = (const float*)d_in[3];
    const float* bhh_f  = (const float*)d_in[4];
    const float* Wih_b  = (const float*)d_in[5];
    const float* Whh_b  = (const float*)d_in[6];
    const float* bih_b  = (const float*)d_in[7];
    const float* bhh_b  = (const float*)d_in[8];
    const float* attn_c = (const float*)d_in[9];
    const float* Wattn  = (const float*)d_in[10];
    const float* battn  = (const float*)d_in[11];
    const float* Wtop   = (const float*)d_in[12];
    const float* btop   = (const float*)d_in[13];
    const float* Wout   = (const float*)d_in[14];
    const float* bout   = (const float*)d_in[15];
    float* out = (float*)d_out;

    prep_kernel<<<(2 * JPAD * KPAD2 + 255) / 256, 256>>>(Whh_f, Whh_b);
    const int npair = MM * (KP / 2) + 2 * 512 * (KP / 2);
    convert_kernel<<<(npair + 255) / 256, 256>>>(x, Wih_f, Wih_b);
    bias2_kernel<<<KK, 320>>>(attn_c, Wattn, battn);

    gemm_gi<<<dim3(8, 512, 2), 256>>>(bih_f, bih_b);

    scan_kernel<<<128, 512>>>(bhh_f, bhh_b);

    ctx_kernel<<<BB * KK, 320>>>(Wattn);
    pool_kernel<<<BB, 512>>>();
    topic_kernel<<<BB, 128>>>(Wtop, btop, Wout, bout, out);
    if (out_size > BB * CLS) {
        reg_partial_kernel<<<BB, 256>>>();
        reg_final_kernel<<<1, BB>>>(out + BB * CLS);
    }
}

// round 16
// speedup vs baseline: 1.3083x; 1.0047x over previous
#include <cuda_runtime.h>
#include <cuda_fp16.h>
#include <cstdint>

#define BB   128
#define TT   512
#define II   300
#define HH   150
#define G3   450
#define KK   6
#define CC   300
#define THD  20
#define CLS  5

#define KP   320
#define MM   (BB * TT)

#define JPAD  464
#define KPAD2 160
#define MTILES 29

#define GSTG  4                        // gemm pipeline stages
#define GA_ELE (128 * 40)
#define GB_ELE (64 * 40)
#define GSMEM ((GSTG * (GA_ELE + GB_ELE)) * 2)   // bytes = 61440

// ---------------- scratch ----------------
__device__ float d_gi_f[(size_t)MM * G3];
__device__ float d_gi_b[(size_t)MM * G3];
__device__ float d_seq [(size_t)MM * 2 * HH];
__device__ float d_hidden[BB * 2 * HH];
__device__ __half d_Whh_h[2][JPAD * KPAD2];
__device__ __half d_Xh[(size_t)MM * KP];
__device__ __half d_Wh[2][512 * KP];
__device__ float d_bias2[KK * 2 * HH];
__device__ float d_context[BB * KK * 2 * HH];
__device__ float d_pooled [BB * KK * 2 * HH];
__device__ float d_regpart[BB];

__device__ __forceinline__ uint32_t smem_u32(const void* p) {
    uint32_t r;
    asm("{ .reg .u64 t; cvta.to.shared.u64 t, %1; cvt.u32.u64 %0, t; }" : "=r"(r) : "l"(p));
    return r;
}

__device__ __forceinline__ void mma16816(float* d, const uint32_t* a, uint32_t b0, uint32_t b1) {
    asm volatile(
        "mma.sync.aligned.m16n8k16.row.col.f32.f16.f16.f32 "
        "{%0,%1,%2,%3}, {%4,%5,%6,%7}, {%8,%9}, {%0,%1,%2,%3};"
        : "+f"(d[0]), "+f"(d[1]), "+f"(d[2]), "+f"(d[3])
        : "r"(a[0]), "r"(a[1]), "r"(a[2]), "r"(a[3]), "r"(b0), "r"(b1));
}

// ---------------- prep: Whh -> half [JPAD][KPAD2], zero padded ----------------
__global__ void prep_kernel(const float* __restrict__ Whh_f, const float* __restrict__ Whh_b) {
    int idx = blockIdx.x * blockDim.x + threadIdx.x;
    int tot = JPAD * KPAD2;
    if (idx < 2 * tot) {
        int d = idx / tot;
        int r = idx - d * tot;
        int j = r / KPAD2, i = r - j * KPAD2;
        const float* W = d ? Whh_b : Whh_f;
        d_Whh_h[d][r] = (j < G3 && i < HH) ? __float2half(W[j * HH + i]) : __float2half(0.f);
    }
}

// ---------------- convert X, Wih -> padded half ----------------
__global__ void convert_kernel(const float* __restrict__ X,
                               const float* __restrict__ Wf, const float* __restrict__ Wb) {
    int idx = blockIdx.x * blockDim.x + threadIdx.x;
    const int totX = MM * (KP / 2);
    if (idx < totX) {
        int m = idx / (KP / 2), kp = idx - m * (KP / 2);
        int k = kp * 2;
        float a = (k < II)     ? X[(size_t)m * II + k]     : 0.f;
        float b = (k + 1 < II) ? X[(size_t)m * II + k + 1] : 0.f;
        reinterpret_cast<__half2*>(d_Xh)[idx] = __floats2half2_rn(a, b);
    } else {
        int r = idx - totX;
        const int totW = 512 * (KP / 2);
        if (r < 2 * totW) {
            int d = r / totW;
            int rr = r - d * totW;
            int n = rr / (KP / 2), kp = rr - n * (KP / 2);
            int k = kp * 2;
            const float* W = d ? Wb : Wf;
            float a = (n < G3 && k < II)     ? W[(size_t)n * II + k]     : 0.f;
            float b = (n < G3 && k + 1 < II) ? W[(size_t)n * II + k + 1] : 0.f;
            reinterpret_cast<__half2*>(d_Wh[d])[rr] = __floats2half2_rn(a, b);
        }
    }
}

// ---------------- bias2 ----------------
__global__ void bias2_kernel(const float* __restrict__ ac, const float* __restrict__ Wattn,
                             const float* __restrict__ battn) {
    int k = blockIdx.x;
    __shared__ float as[CC];
    int tid = threadIdx.x;
    if (tid < CC) as[tid] = ac[k * CC + tid];
    __syncthreads();
    if (tid < 2 * HH) {
        float acc = battn[k * 2 * HH + tid];
        const float* w = Wattn + (size_t)k * (CC + 2 * HH) * (2 * HH) + tid;
        #pragma unroll 4
        for (int c = 0; c < CC; ++c) acc += as[c] * w[(size_t)c * (2 * HH)];
        d_bias2[k * 2 * HH + tid] = acc;
    }
}

// ---------------- gi GEMM: 4-stage cp.async pipeline, one barrier per iter ----------------
__global__ void __launch_bounds__(256, 2)
gemm_gi(const float* __restrict__ bf, const float* __restrict__ bb) {
    extern __shared__ __align__(16) __half gsm[];
    __half* AsmP = gsm;                       // GSTG * GA_ELE
    __half* BsmP = gsm + GSTG * GA_ELE;       // GSTG * GB_ELE
    int which = blockIdx.z;
    const __half* Wh  = d_Wh[which];
    const float* bias = which ? bb : bf;
    float* O          = which ? d_gi_b : d_gi_f;

    int m0 = blockIdx.y * 128;
    int n0 = blockIdx.x * 64;
    int tid = threadIdx.x;
    int wid = tid >> 5, lane = tid & 31;
    int warpM = (wid & 3) * 32;
    int warpN = (wid >> 2) * 32;
    int gr = lane >> 2, t4 = lane & 3;

    float acc[2][4][4];
    #pragma unroll
    for (int mt = 0; mt < 2; ++mt)
        #pragma unroll
        for (int nt = 0; nt < 4; ++nt)
            #pragma unroll
            for (int q = 0; q < 4; ++q) acc[mt][nt][q] = 0.f;

    int ar = tid >> 1, ac = (tid & 1) * 2;
    int br = tid >> 2, bc = tid & 3;
    const __half* Xsrc = d_Xh + (size_t)(m0 + ar) * KP + ac * 8;
    const __half* Wsrc = Wh   + (size_t)(n0 + br) * KP + bc * 8;
    uint32_t aBase = smem_u32(AsmP);
    uint32_t bBase = smem_u32(BsmP);
    const uint32_t aBuf = GA_ELE * 2, bBuf = GB_ELE * 2;
    uint32_t aDst = aBase + (ar * 40 + ac * 8) * 2;
    uint32_t bDst = bBase + (br * 40 + bc * 8) * 2;

    const int NT = KP / 32;   // 10

    auto issue = [&](int it) {
        int buf = it & 3;
        const __half* as_ = Xsrc + it * 32;
        const __half* bs_ = Wsrc + it * 32;
        uint32_t ad = aDst + buf * aBuf;
        uint32_t bd = bDst + buf * bBuf;
        asm volatile(
            "cp.async.cg.shared.global [%0], [%1], 16;\n\t"
            "cp.async.cg.shared.global [%2], [%3], 16;\n\t"
            "cp.async.cg.shared.global [%4], [%5], 16;\n\t"
            "cp.async.commit_group;"
            :: "r"(ad), "l"(as_), "r"(ad + 16), "l"(as_ + 8), "r"(bd), "l"(bs_)
            : "memory");
    };

    uint32_t aRow[2], bRow[2];
    #pragma unroll
    for (int mt = 0; mt < 2; ++mt)
        aRow[mt] = ((warpM + mt * 16 + (lane & 15)) * 40 + ((lane >> 4) * 8)) * 2;
    #pragma unroll
    for (int p2 = 0; p2 < 2; ++p2)
        bRow[p2] = ((warpN + p2 * 16 + ((lane & 16) ? 8 : 0) + (lane & 7)) * 40
                    + ((lane & 8) ? 8 : 0)) * 2;

    issue(0);
    issue(1);
    issue(2);

    for (int it = 0; it < NT; ++it) {
        // ensure group `it` is complete (taper at tail)
        if (it < NT - 3)      asm volatile("cp.async.wait_group 2;" ::: "memory");
        else if (it == NT - 3) asm volatile("cp.async.wait_group 2;" ::: "memory");
        else if (it == NT - 2) asm volatile("cp.async.wait_group 1;" ::: "memory");
        else                   asm volatile("cp.async.wait_group 0;" ::: "memory");
        __syncthreads();   // separates iter it-1's reads from the issue below
        if (it + 3 < NT) issue(it + 3);   // writes buf (it+3)&3 == (it-1)&3, reads done

        int buf = it & 3;
        uint32_t aB = aBase + buf * aBuf;
        uint32_t bB = bBase + buf * bBuf;
        #pragma unroll
        for (int kk = 0; kk < 32; kk += 16) {
            uint32_t a[2][4], b[2][4];
            #pragma unroll
            for (int mt = 0; mt < 2; ++mt)
                asm volatile("ldmatrix.sync.aligned.m8n8.x4.shared.b16 {%0,%1,%2,%3}, [%4];"
                             : "=r"(a[mt][0]), "=r"(a[mt][1]), "=r"(a[mt][2]), "=r"(a[mt][3])
                             : "r"(aB + aRow[mt] + kk * 2));
            #pragma unroll
            for (int p2 = 0; p2 < 2; ++p2)
                asm volatile("ldmatrix.sync.aligned.m8n8.x4.shared.b16 {%0,%1,%2,%3}, [%4];"
                             : "=r"(b[p2][0]), "=r"(b[p2][1]), "=r"(b[p2][2]), "=r"(b[p2][3])
                             : "r"(bB + bRow[p2] + kk * 2));
            #pragma unroll
            for (int mt = 0; mt < 2; ++mt)
                #pragma unroll
                for (int nt = 0; nt < 4; ++nt) {
                    uint32_t b0 = b[nt >> 1][(nt & 1) * 2];
                    uint32_t b1 = b[nt >> 1][(nt & 1) * 2 + 1];
                    asm volatile(
                        "mma.sync.aligned.m16n8k16.row.col.f32.f16.f16.f32 "
                        "{%0,%1,%2,%3}, {%4,%5,%6,%7}, {%8,%9}, {%0,%1,%2,%3};"
                        : "+f"(acc[mt][nt][0]), "+f"(acc[mt][nt][1]),
                          "+f"(acc[mt][nt][2]), "+f"(acc[mt][nt][3])
                        : "r"(a[mt][0]), "r"(a[mt][1]), "r"(a[mt][2]), "r"(a[mt][3]),
                          "r"(b0), "r"(b1));
                }
        }
    }

    #pragma unroll
    for (int mt = 0; mt < 2; ++mt) {
        #pragma unroll
        for (int hf = 0; hf < 2; ++hf) {
            int m = m0 + warpM + mt * 16 + gr + hf * 8;
            float* Orow = O + (size_t)m * G3;
            #pragma unroll
            for (int nt = 0; nt < 4; ++nt) {
                int col = n0 + warpN + nt * 8 + 2 * t4;
                if (col < G3) {
                    float v0 = acc[mt][nt][hf * 2 + 0] + bias[col];
                    float v1 = acc[mt][nt][hf * 2 + 1] + bias[col + 1];
                    *reinterpret_cast<float2*>(Orow + col) = make_float2(v0, v1);
                }
            }
        }
    }
}

// ---------------- persistent bidirectional GRU scan (R14/R15 proven version) -------------
__device__ __forceinline__ float sigm(float x) { return 1.f / (1.f + __expf(-x)); }
__device__ __forceinline__ float fast_tanh(float x) {
    float y; asm("tanh.approx.f32 %0, %1;" : "=f"(y) : "f"(x)); return y;
}

__global__ void __launch_bounds__(512, 1)
scan_kernel(const float* __restrict__ bhh_f, const float* __restrict__ bhh_b) {
    __shared__ __align__(8) float2 ghb2[JPAD];
    __shared__ __align__(4) __half h_s[2][KPAD2];

    int bb  = blockIdx.x;
    int dir = bb >> 6;
    int p   = bb & 63;
    int b0  = 2 * p, b1 = b0 + 1;
    const float* gi  = dir ? d_gi_b : d_gi_f;
    const float* bhh = dir ? bhh_b : bhh_f;
    const __half* Wd = d_Whh_h[dir];
    int tid = threadIdx.x;
    int wid = tid >> 5, lane = tid & 31;
    int g = lane >> 2, tig = lane & 3;

    for (int i = tid; i < 2 * KPAD2; i += 512)
        reinterpret_cast<__half*>(h_s)[i] = __float2half(0.f);

    const int t1 = wid;
    const int t2 = 16 + wid;
    const bool has2 = (t2 < MTILES);

    uint32_t A1[10][4], A2[10][4];
    {
        const __half* r0 = Wd + (size_t)(t1 * 16 + g) * KPAD2;
        const __half* r8 = r0 + 8 * KPAD2;
        #pragma unroll
        for (int kt = 0; kt < 10; ++kt) {
            int k0 = kt * 16 + tig * 2;
            A1[kt][0] = *reinterpret_cast<const uint32_t*>(r0 + k0);
            A1[kt][1] = *reinterpret_cast<const uint32_t*>(r8 + k0);
            A1[kt][2] = *reinterpret_cast<const uint32_t*>(r0 + k0 + 8);
            A1[kt][3] = *reinterpret_cast<const uint32_t*>(r8 + k0 + 8);
        }
        if (has2) {
            const __half* s0 = Wd + (size_t)(t2 * 16 + g) * KPAD2;
            const __half* s8 = s0 + 8 * KPAD2;
            #pragma unroll
            for (int kt = 0; kt < 10; ++kt) {
                int k0 = kt * 16 + tig * 2;
                A2[kt][0] = *reinterpret_cast<const uint32_t*>(s0 + k0);
                A2[kt][1] = *reinterpret_cast<const uint32_t*>(s8 + k0);
                A2[kt][2] = *reinterpret_cast<const uint32_t*>(s0 + k0 + 8);
                A2[kt][3] = *reinterpret_cast<const uint32_t*>(s8 + k0 + 8);
            }
        }
    }

    float cb1a, cb1b, cb2a = 0.f, cb2b = 0.f;
    {
        int m = t1 * 16 + g;
        cb1a = (m < G3) ? bhh[m] : 0.f;
        cb1b = (m + 8 < G3) ? bhh[m + 8] : 0.f;
        if (has2) {
            int m2 = t2 * 16 + g;
            cb2a = (m2 < G3) ? bhh[m2] : 0.f;
            cb2b = (m2 + 8 < G3) ? bhh[m2 + 8] : 0.f;
        }
    }

    const int e = tid;
    const bool ge = (e < 2 * HH);
    const int row = (e < HH) ? 0 : 1;
    const int jj  = e - row * HH;
    const size_t rowbase = (size_t)(row ? b1 : b0) * TT;

    __syncthreads();

    float g_r = 0.f, g_z = 0.f, g_n = 0.f;
    if (ge) {
        int t0 = dir ? (TT - 1) : 0;
        size_t gb = (rowbase + t0) * G3 + jj;
        g_r = gi[gb]; g_z = gi[gb + HH]; g_n = gi[gb + 2 * HH];
    }

    for (int s = 0; s < TT; ++s) {
        int t = dir ? (TT - 1 - s) : s;
        float nr = 0.f, nz = 0.f, nn = 0.f;
        if (ge && s + 1 < TT) {
            int tn = dir ? (TT - 2 - s) : (s + 1);
            size_t gb = (rowbase + tn) * G3 + jj;
            nr = gi[gb]; nz = gi[gb + HH]; nn = gi[gb + 2 * HH];
        }

        {
            float d1a[4] = {cb1a, cb1a, cb1b, cb1b};
            float d1b[4] = {0.f, 0.f, 0.f, 0.f};
            float d2a[4] = {cb2a, cb2a, cb2b, cb2b};
            float d2b[4] = {0.f, 0.f, 0.f, 0.f};
            uint32_t Bv[10][2];
            #pragma unroll
            for (int kt = 0; kt < 10; ++kt) {
                Bv[kt][0] = 0; Bv[kt][1] = 0;
                if (g < 2) {
                    const __half* hp = &h_s[g][kt * 16 + tig * 2];
                    Bv[kt][0] = *reinterpret_cast<const uint32_t*>(hp);
                    Bv[kt][1] = *reinterpret_cast<const uint32_t*>(hp + 8);
                }
            }
            #pragma unroll
            for (int kt = 0; kt < 10; kt += 2) {
                mma16816(d1a, A1[kt],     Bv[kt][0],     Bv[kt][1]);
                mma16816(d1b, A1[kt + 1], Bv[kt + 1][0], Bv[kt + 1][1]);
                if (has2) {
                    mma16816(d2a, A2[kt],     Bv[kt][0],     Bv[kt][1]);
                    mma16816(d2b, A2[kt + 1], Bv[kt + 1][0], Bv[kt + 1][1]);
                }
            }
            if (tig == 0) {
                int m = t1 * 16 + g;
                ghb2[m]     = make_float2(d1a[0] + d1b[0], d1a[1] + d1b[1]);
                ghb2[m + 8] = make_float2(d1a[2] + d1b[2], d1a[3] + d1b[3]);
                if (has2) {
                    int m2 = t2 * 16 + g;
                    ghb2[m2]     = make_float2(d2a[0] + d2b[0], d2a[1] + d2b[1]);
                    ghb2[m2 + 8] = make_float2(d2a[2] + d2b[2], d2a[3] + d2b[3]);
                }
            }
        }
        __syncthreads();

        if (ge) {
            const float* gb = reinterpret_cast<const float*>(ghb2);
            float hr = gb[jj * 2 + row];
            float hz = gb[(jj + HH) * 2 + row];
            float hn = gb[(jj + 2 * HH) * 2 + row];
            float rg = sigm(g_r + hr);
            float zg = sigm(g_z + hz);
            float ng = fast_tanh(g_n + rg * hn);
            float hp = __half2float(h_s[row][jj]);
            float hv = (1.f - zg) * ng + zg * hp;
            h_s[row][jj] = __float2half(hv);
            d_seq[(rowbase + t) * (2 * HH) + dir * HH + jj] = hv;
        }
        __syncthreads();
        g_r = nr; g_z = nz; g_n = nn;
    }
    if (ge) {
        float hv = __half2float(h_s[row][jj]);
        d_hidden[(size_t)(row ? b1 : b0) * (2 * HH) + dir * HH + jj] = hv;
    }
}

// ---------------- context: tiled mini-GEMM, Wattn read once ------------------------------
// grid (KK, 15); block 128 threads (one per batch row); each block does d-cols [dc*20, +20).
__global__ void ctx_kernel(const float* __restrict__ Wattn) {
    int k = blockIdx.x, dc = blockIdx.y;
    int d0 = dc * THD;                   // 20-wide column chunk
    int b = threadIdx.x;                 // 128
    __shared__ float Wsm[50][THD];

    float acc[THD];
    #pragma unroll
    for (int j = 0; j < THD; ++j) acc[j] = d_bias2[k * 2 * HH + d0 + j];

    const float* Wbase = Wattn + ((size_t)k * (CC + 2 * HH) + CC) * (2 * HH) + d0;
    const float* hrow  = d_hidden + (size_t)b * (2 * HH);

    for (int c0 = 0; c0 < 2 * HH; c0 += 50) {
        // cooperative load of W[c0..c0+49][d0..d0+19]
        for (int idx = b; idx < 50 * THD; idx += 128) {
            int c = idx / THD, j = idx - c * THD;
            Wsm[c][j] = Wbase[(size_t)(c0 + c) * (2 * HH) + j];
        }
        __syncthreads();
        #pragma unroll 10
        for (int c = 0; c < 50; ++c) {
            float h = hrow[c0 + c];
            #pragma unroll
            for (int j = 0; j < THD; ++j) acc[j] = fmaf(h, Wsm[c][j], acc[j]);
        }
        __syncthreads();
    }
    float* dst = d_context + ((size_t)b * KK + k) * (2 * HH) + d0;
    #pragma unroll
    for (int j = 0; j < THD; ++j) dst[j] = tanhf(acc[j]);
}

// ---------------- energy -> softmax(t) -> pooled ----------------
__global__ void pool_kernel() {
    int b = blockIdx.x;
    __shared__ float ctx[KK][2 * HH];
    __shared__ float en[TT][KK];
    int tid = threadIdx.x;              // 512
    int w = tid >> 5, lane = tid & 31;
    for (int i = tid; i < KK * 2 * HH; i += 512)
        ctx[i / (2 * HH)][i % (2 * HH)] = d_context[(size_t)b * KK * 2 * HH + i];
    __syncthreads();
    for (int t = w; t < TT; t += 16) {
        const float* srow = d_seq + ((size_t)b * TT + t) * (2 * HH);
        float pk[KK] = {0, 0, 0, 0, 0, 0};
        for (int d = lane; d < 2 * HH; d += 32) {
            float s = srow[d];
            #pragma unroll
            for (int k = 0; k < KK; ++k) pk[k] = fmaf(s, ctx[k][d], pk[k]);
        }
        #pragma unroll
        for (int k = 0; k < KK; ++k) {
            float v = pk[k];
            for (int off = 16; off; off >>= 1) v += __shfl_xor_sync(~0u, v, off);
            if (lane == 0) en[t][k] = v;
        }
    }
    __syncthreads();
    if (w < KK) {
        float mx = -1e30f;
        for (int t = lane; t < TT; t += 32) mx = fmaxf(mx, en[t][w]);
        for (int off = 16; off; off >>= 1) mx = fmaxf(mx, __shfl_xor_sync(~0u, mx, off));
        float sum = 0.f;
        for (int t = lane; t < TT; t += 32) { float e2 = __expf(en[t][w] - mx); en[t][w] = e2; sum += e2; }
        for (int off = 16; off; off >>= 1) sum += __shfl_xor_sync(~0u, sum, off);
        float inv = 1.f / sum;
        for (int t = lane; t < TT; t += 32) en[t][w] *= inv;
    }
    __syncthreads();
    if (tid < HH) {
        int d = tid * 2;
        float acc0[KK] = {0, 0, 0, 0, 0, 0};
        float acc1[KK] = {0, 0, 0, 0, 0, 0};
        const float* sp = d_seq + (size_t)b * TT * (2 * HH) + d;
        #pragma unroll 8
        for (int t = 0; t < TT; ++t) {
            float2 s = *reinterpret_cast<const float2*>(sp + (size_t)t * (2 * HH));
            #pragma unroll
            for (int k = 0; k < KK; ++k) {
                float pr = en[t][k];
                acc0[k] = fmaf(s.x, pr, acc0[k]);
                acc1[k] = fmaf(s.y, pr, acc1[k]);
            }
        }
        #pragma unroll
        for (int k = 0; k < KK; ++k) {
            float* dst = d_pooled + ((size_t)b * KK + k) * (2 * HH) + d;
            dst[0] = acc0[k];
            dst[1] = acc1[k];
        }
    }
}

// ---------------- topic -> logits -> softmax ----------------
__global__ void topic_kernel(const float* __restrict__ Wtop, const float* __restrict__ btop,
                             const float* __restrict__ Wout, const float* __restrict__ bout,
                             float* __restrict__ out) {
    int b = blockIdx.x;
    __shared__ float ps[KK * 2 * HH];
    __shared__ float feats[KK * THD];
    __shared__ float lg[CLS];
    int tid = threadIdx.x;
    for (int i = tid; i < KK * 2 * HH; i += 128) ps[i] = d_pooled[(size_t)b * KK * 2 * HH + i];
    __syncthreads();
    if (tid < KK * THD) {
        int k = tid / THD, th = tid - k * THD;
        float acc = btop[tid];
        const float* wp = Wtop + (size_t)k * (2 * HH) * THD + th;
        #pragma unroll 4
        for (int d = 0; d < 2 * HH; ++d) acc += ps[k * 2 * HH + d] * wp[d * THD];
        feats[tid] = fmaxf(acc, 0.f);
    }
    __syncthreads();
    if (tid < CLS) {
        float acc = bout[tid];
        for (int e2 = 0; e2 < KK * THD; ++e2) acc += feats[e2] * Wout[e2 * CLS + tid];
        lg[tid] = acc;
    }
    __syncthreads();
    if (tid < CLS) {
        float mx = lg[0];
        #pragma unroll
        for (int c = 1; c < CLS; ++c) mx = fmaxf(mx, lg[c]);
        float sum = 0.f;
        #pragma unroll
        for (int c = 0; c < CLS; ++c) sum += __expf(lg[c] - mx);
        out[b * CLS + tid] = __expf(lg[tid] - mx) / sum;
    }
}

// ---------------- orthogonality regularizer ----------------
__global__ void reg_partial_kernel() {
    int b = blockIdx.x;
    __shared__ float cs[KK * 2 * HH];
    __shared__ float D[KK * KK];
    int tid = threadIdx.x;
    int w = tid >> 5, lane = tid & 31;
    for (int i = tid; i < KK * 2 * HH; i += 256) cs[i] = d_context[(size_t)b * KK * 2 * HH + i];
    __syncthreads();
    for (int p2 = w; p2 < KK * KK; p2 += 8) {
        int k = p2 / KK, j = p2 - k * KK;
        float v = 0.f;
        for (int d = lane; d < 2 * HH; d += 32) v += cs[k * 2 * HH + d] * cs[j * 2 * HH + d];
        for (int off = 16; off; off >>= 1) v += __shfl_xor_sync(~0u, v, off);
        if (lane == 0) D[p2] = v;
    }
    __syncthreads();
    if (tid == 0) {
        float nk[KK];
        #pragma unroll
        for (int k = 0; k < KK; ++k) nk[k] = fmaxf(sqrtf(D[k * KK + k]), 1e-12f);
        float S = 0.f;
        for (int k = 0; k < KK; ++k)
            for (int j = 0; j < KK; ++j) {
                float g = D[k * KK + j] / (nk[k] * nk[j]) - (k == j ? 1.f : 0.f);
                S += g * g;
            }
        d_regpart[b] = sqrtf(S);
    }
}

__global__ void reg_final_kernel(float* __restrict__ regout) {
    __shared__ float s[BB];
    int tid = threadIdx.x;
    s[tid] = d_regpart[tid];
    __syncthreads();
    for (int off = 64; off; off >>= 1) {
        if (tid < off) s[tid] += s[tid + off];
        __syncthreads();
    }
    if (tid == 0) *regout = s[0] / (float)BB;
}

// ---------------- launch ------------------------------------------------------------------
extern "C" void kernel_launch(void* const* d_in, const int* in_sizes, int n_in,
                              void* d_out, int out_size) {
    const float* x      = (const float*)d_in[0];
    const float* Wih_f  = (const float*)d_in[1];
    const float* Whh_f  = (const float*)d_in[2];
    const float* bih_f  = (const float*)d_in[3];
    const float* bhh_f  = (const float*)d_in[4];
    const float* Wih_b  = (const float*)d_in[5];
    const float* Whh_b  = (const float*)d_in[6];
    const float* bih_b  = (const float*)d_in[7];
    const float* bhh_b  = (const float*)d_in[8];
    const float* attn_c = (const float*)d_in[9];
    const float* Wattn  = (const float*)d_in[10];
    const float* battn  = (const float*)d_in[11];
    const float* Wtop   = (const float*)d_in[12];
    const float* btop   = (const float*)d_in[13];
    const float* Wout   = (const float*)d_in[14];
    const float* bout   = (const float*)d_in[15];
    float* out = (float*)d_out;

    cudaFuncSetAttribute(gemm_gi, cudaFuncAttributeMaxDynamicSharedMemorySize, GSMEM);

    prep_kernel<<<(2 * JPAD * KPAD2 + 255) / 256, 256>>>(Whh_f, Whh_b);
    const int npair = MM * (KP / 2) + 2 * 512 * (KP / 2);
    convert_kernel<<<(npair + 255) / 256, 256>>>(x, Wih_f, Wih_b);
    bias2_kernel<<<KK, 320>>>(attn_c, Wattn, battn);

    gemm_gi<<<dim3(8, 512, 2), 256, GSMEM>>>(bih_f, bih_b);

    scan_kernel<<<128, 512>>>(bhh_f, bhh_b);

    ctx_kernel<<<dim3(KK, 15), 128>>>(Wattn);
    pool_kernel<<<BB, 512>>>();
    topic_kernel<<<BB, 128>>>(Wtop, btop, Wout, bout, out);
    if (out_size > BB * CLS) {
        reg_partial_kernel<<<BB, 256>>>();
        reg_final_kernel<<<1, BB>>>(out + BB * CLS);
    }
}